// round 2
// baseline (speedup 1.0000x reference)
#include <cuda_runtime.h>
#include <cuda_fp8.h>
#include <math.h>

#define B 32
#define S 4096
#define H 16
#define KV_LORA 512
#define NOPE 128
#define ROPE 64
#define QKD 192
#define VD 128
#define QIN 1536
#define HID 2048
#define DKV 576
#define NQ (H*QKD)
#define SCALEF 0.07216878364870323f

#define NCHUNK 16
#define CHUNK 256
#define TILE 16
#define KSQP 6
#define KSO 8

// ---------------- device scratch (static allocations are allowed) ----------------
static __device__ unsigned g_amax[2];
static __device__ float g_WKd[H*KV_LORA*NOPE];        // 4 MB
static __device__ float g_WVd[H*VD*KV_LORA];          // 4 MB
static __device__ float g_qp_part[KSQP][B*NQ];        // 2.4 MB
static __device__ float g_qf[B*H*DKV];                // 1.2 MB
static __device__ float g_newkv[B*DKV];
static __device__ float g_m[B*H*NCHUNK];
static __device__ float g_l[B*H*NCHUNK];
static __device__ float g_opart[B*H*NCHUNK*KV_LORA];  // 16.8 MB
static __device__ float g_t[B*HID];
static __device__ float g_out_part[KSO][B*HID];       // 2.1 MB

// ---------------- reset ----------------
__global__ void k_reset(){
  if (threadIdx.x < 2) g_amax[threadIdx.x] = 0u;
}

// ---------------- global abs-max of W_K and W_V ----------------
__global__ void k_amax(const float* __restrict__ WK, const float* __restrict__ WV){
  const int N = H*KV_LORA*NOPE;
  float m0 = 0.f, m1 = 0.f;
  for (int i = blockIdx.x*blockDim.x + threadIdx.x; i < N; i += gridDim.x*blockDim.x){
    m0 = fmaxf(m0, fabsf(WK[i]));
    m1 = fmaxf(m1, fabsf(WV[i]));
  }
  #pragma unroll
  for (int off = 16; off; off >>= 1){
    m0 = fmaxf(m0, __shfl_xor_sync(0xffffffffu, m0, off));
    m1 = fmaxf(m1, __shfl_xor_sync(0xffffffffu, m1, off));
  }
  __shared__ float s0[8], s1[8];
  int w = threadIdx.x >> 5;
  if ((threadIdx.x & 31) == 0){ s0[w] = m0; s1[w] = m1; }
  __syncthreads();
  if (threadIdx.x == 0){
    #pragma unroll
    for (int i = 1; i < 8; i++){ m0 = fmaxf(m0, s0[i]); m1 = fmaxf(m1, s1[i]); }
    atomicMax(&g_amax[0], __float_as_uint(m0));  // valid for non-negative floats
    atomicMax(&g_amax[1], __float_as_uint(m1));
  }
}

// ---------------- fp8 e4m3 fake-quant round-trip ----------------
__global__ void k_quant(const float* __restrict__ WK, const float* __restrict__ WV){
  const int N = H*KV_LORA*NOPE;
  float aK = fmaxf(__uint_as_float(g_amax[0]), 1e-10f);
  float aV = fmaxf(__uint_as_float(g_amax[1]), 1e-10f);
  float sK = 448.f / aK, sV = 448.f / aV;
  for (int i = blockIdx.x*blockDim.x + threadIdx.x; i < N; i += gridDim.x*blockDim.x){
    float x = fminf(fmaxf(WK[i]*sK, -448.f), 448.f);
    __nv_fp8_storage_t f8 = __nv_cvt_float_to_fp8(x, __NV_SATFINITE, __NV_E4M3);
    g_WKd[i] = __half2float(__half(__nv_cvt_fp8_to_halfraw(f8, __NV_E4M3))) / sK;
    float y = fminf(fmaxf(WV[i]*sV, -448.f), 448.f);
    __nv_fp8_storage_t g8 = __nv_cvt_float_to_fp8(y, __NV_SATFINITE, __NV_E4M3);
    g_WVd[i] = __half2float(__half(__nv_cvt_fp8_to_halfraw(g8, __NV_E4M3))) / sV;
  }
}

// ---------------- qp = q @ Wq  (split-K=6 partials) ----------------
__global__ void __launch_bounds__(256) k_qp(const float* __restrict__ q,
                                            const float* __restrict__ Wq){
  __shared__ float xs[B][256];
  int cb = blockIdx.x, ks = blockIdx.y;
  int col = cb*32 + (threadIdx.x & 31);
  int rg  = threadIdx.x >> 5;
  int k0  = ks*256;
  for (int idx = threadIdx.x; idx < B*256; idx += 256){
    int r = idx >> 8, k = idx & 255;
    xs[r][k] = q[r*QIN + k0 + k];
  }
  __syncthreads();
  float a0=0.f, a1=0.f, a2=0.f, a3=0.f;
  const float* wp = Wq + (size_t)k0*NQ + col;
  #pragma unroll 4
  for (int k = 0; k < 256; k++){
    float w = wp[(size_t)k*NQ];
    a0 += xs[rg*4+0][k]*w;
    a1 += xs[rg*4+1][k]*w;
    a2 += xs[rg*4+2][k]*w;
    a3 += xs[rg*4+3][k]*w;
  }
  float* op = g_qp_part[ks];
  op[(rg*4+0)*NQ + col] = a0;
  op[(rg*4+1)*NQ + col] = a1;
  op[(rg*4+2)*NQ + col] = a2;
  op[(rg*4+3)*NQ + col] = a3;
}

// ---------------- build qf = [q_nope @ W_Kd^T, rope(q_pe)], and new_kv ----------------
__global__ void __launch_bounds__(128) k_qf(const float* __restrict__ kc,
                                            const float* __restrict__ kpe,
                                            const int* __restrict__ kv_lens){
  int h = blockIdx.x, b = blockIdx.y;
  int tid = threadIdx.x;
  __shared__ float qn[NOPE];
  __shared__ float qpe[ROPE];
  int base = b*NQ + h*QKD;
  if (tid < NOPE){
    float s = 0.f;
    #pragma unroll
    for (int ks = 0; ks < KSQP; ks++) s += g_qp_part[ks][base + tid];
    qn[tid] = s;
  }
  if (tid < ROPE){
    float s = 0.f;
    #pragma unroll
    for (int ks = 0; ks < KSQP; ks++) s += g_qp_part[ks][base + NOPE + tid];
    qpe[tid] = s;
  }
  __syncthreads();
  float* qf = g_qf + (b*H + h)*DKV;
  for (int c = tid; c < KV_LORA; c += 128){
    const float4* w = (const float4*)(g_WKd + (size_t)(h*KV_LORA + c)*NOPE);
    float s = 0.f;
    #pragma unroll
    for (int d4 = 0; d4 < NOPE/4; d4++){
      float4 wv = w[d4];
      float4 qv = *(const float4*)(qn + d4*4);
      s += qv.x*wv.x + qv.y*wv.y + qv.z*wv.z + qv.w*wv.w;
    }
    qf[c] = s;
  }
  int pos = kv_lens[b];
  if (tid < 32){
    int i = tid;
    double e   = (2.0*i)/64.0;
    double inv = exp(-e * 9.210340371976184);   // ln(10000)
    double ang = (double)pos * inv;
    float cs = (float)cos(ang), sn = (float)sin(ang);
    float x1 = qpe[i], x2 = qpe[i+32];
    qf[KV_LORA + i]      = x1*cs - x2*sn;
    qf[KV_LORA + 32 + i] = x2*cs + x1*sn;
    if (h == 0){
      float k1 = kpe[b*ROPE + i], k2 = kpe[b*ROPE + 32 + i];
      g_newkv[b*DKV + KV_LORA + i]      = k1*cs - k2*sn;
      g_newkv[b*DKV + KV_LORA + 32 + i] = k2*cs + k1*sn;
    }
  }
  if (h == 0){
    for (int c = tid; c < KV_LORA; c += 128)
      g_newkv[b*DKV + c] = kc[b*KV_LORA + c];
  }
}

// ---------------- split-KV flash attention: 16 heads per CTA, 2 heads per warp ----------------
__global__ void __launch_bounds__(256) k_attn(const float* __restrict__ kv_cache,
                                              const int* __restrict__ kv_lens){
  int chunk = blockIdx.x, b = blockIdx.y;
  int warp = threadIdx.x >> 5, lane = threadIdx.x & 31;
  int h0 = warp*2;
  int len = kv_lens[b];
  int s_begin = chunk*CHUNK;
  int s_end = min(s_begin + CHUNK, len + 1);   // row s==len uses new_kv

  __shared__ float kvs[TILE][DKV];
  __shared__ float ps[H][TILE];

  float qr0[18], qr1[18];
  const float* qf0 = g_qf + (size_t)(b*H + h0)*DKV;
  #pragma unroll
  for (int j = 0; j < 18; j++){ qr0[j] = qf0[j*32 + lane]; qr1[j] = qf0[DKV + j*32 + lane]; }

  float acc0[16], acc1[16];
  #pragma unroll
  for (int j = 0; j < 16; j++){ acc0[j] = 0.f; acc1[j] = 0.f; }
  float m0 = -INFINITY, m1 = -INFINITY, l0 = 0.f, l1 = 0.f;

  for (int t0 = s_begin; t0 < s_end; t0 += TILE){
    int rows = min(TILE, s_end - t0);
    __syncthreads();
    for (int idx = threadIdx.x; idx < rows*(DKV/4); idx += 256){
      int r  = idx / (DKV/4);
      int c4 = idx - r*(DKV/4);
      int s  = t0 + r;
      const float4* src = (s == len) ? (const float4*)(g_newkv + b*DKV)
                                     : (const float4*)(kv_cache + ((size_t)b*S + s)*DKV);
      ((float4*)kvs[r])[c4] = src[c4];
    }
    __syncthreads();

    // scores for 2 heads (q in regs, kv row read once per head-pair)
    for (int r = 0; r < rows; r++){
      float a = 0.f, c = 0.f;
      #pragma unroll
      for (int j = 0; j < 18; j++){
        float kvv = kvs[r][j*32 + lane];
        a += qr0[j]*kvv; c += qr1[j]*kvv;
      }
      #pragma unroll
      for (int off = 16; off; off >>= 1){
        a += __shfl_xor_sync(0xffffffffu, a, off);
        c += __shfl_xor_sync(0xffffffffu, c, off);
      }
      if (lane == 0){ ps[h0][r] = a*SCALEF; ps[h0+1][r] = c*SCALEF; }
    }
    __syncwarp();

    float tm0 = -INFINITY, tm1 = -INFINITY;
    for (int r = 0; r < rows; r++){
      tm0 = fmaxf(tm0, ps[h0][r]);
      tm1 = fmaxf(tm1, ps[h0+1][r]);
    }
    float nm0 = fmaxf(m0, tm0), nm1 = fmaxf(m1, tm1);
    float cf0 = __expf(m0 - nm0), cf1 = __expf(m1 - nm1);
    m0 = nm0; m1 = nm1;

    float p0 = 0.f, p1 = 0.f;
    if (lane < rows){
      p0 = __expf(ps[h0][lane]   - nm0);
      p1 = __expf(ps[h0+1][lane] - nm1);
    }
    float sp0 = p0, sp1 = p1;
    #pragma unroll
    for (int off = 16; off; off >>= 1){
      sp0 += __shfl_xor_sync(0xffffffffu, sp0, off);
      sp1 += __shfl_xor_sync(0xffffffffu, sp1, off);
    }
    l0 = l0*cf0 + sp0; l1 = l1*cf1 + sp1;
    if (lane < rows){ ps[h0][lane] = p0; ps[h0+1][lane] = p1; }
    __syncwarp();

    #pragma unroll
    for (int j = 0; j < 16; j++){ acc0[j] *= cf0; acc1[j] *= cf1; }
    for (int r = 0; r < rows; r++){
      float pp0 = ps[h0][r], pp1 = ps[h0+1][r];
      #pragma unroll
      for (int j = 0; j < 16; j++){
        float kvv = kvs[r][j*32 + lane];
        acc0[j] += pp0*kvv; acc1[j] += pp1*kvv;
      }
    }
  }

  int base = (b*H + h0)*NCHUNK + chunk;
  if (lane == 0){
    g_m[base] = m0; g_l[base] = l0;
    g_m[base + NCHUNK] = m1; g_l[base + NCHUNK] = l1;
  }
  #pragma unroll
  for (int j = 0; j < 16; j++){
    g_opart[(size_t)base*KV_LORA + j*32 + lane]           = acc0[j];
    g_opart[(size_t)(base + NCHUNK)*KV_LORA + j*32 + lane] = acc1[j];
  }
}

// ---------------- combine split-softmax partials + apply W_Vd ----------------
__global__ void __launch_bounds__(128) k_combine(){
  int h = blockIdx.x, b = blockIdx.y;
  int tid = threadIdx.x;
  int base = (b*H + h)*NCHUNK;
  float mstar = -INFINITY;
  #pragma unroll
  for (int c = 0; c < NCHUNK; c++) mstar = fmaxf(mstar, g_m[base + c]);
  float ecf[NCHUNK];
  float lstar = 0.f;
  #pragma unroll
  for (int c = 0; c < NCHUNK; c++){
    float e = expf(g_m[base + c] - mstar);
    ecf[c] = e;
    lstar += e * g_l[base + c];
  }
  float inv_l = 1.f / lstar;
  __shared__ float osh[KV_LORA];
  for (int d = tid; d < KV_LORA; d += 128){
    float s = 0.f;
    #pragma unroll
    for (int c = 0; c < NCHUNK; c++)
      s += ecf[c] * g_opart[(size_t)(base + c)*KV_LORA + d];
    osh[d] = s * inv_l;
  }
  __syncthreads();
  const float4* w = (const float4*)(g_WVd + (size_t)(h*VD + tid)*KV_LORA);
  float s = 0.f;
  #pragma unroll 4
  for (int c4 = 0; c4 < KV_LORA/4; c4++){
    float4 wv = w[c4];
    float4 ov = *(const float4*)(osh + c4*4);
    s += ov.x*wv.x + ov.y*wv.y + ov.z*wv.z + ov.w*wv.w;
  }
  g_t[b*HID + h*VD + tid] = s;
}

// ---------------- out = t @ Wo (split-K=8 partials) ----------------
__global__ void __launch_bounds__(256) k_out(const float* __restrict__ Wo){
  __shared__ float xs[B][256];
  int cb = blockIdx.x, ks = blockIdx.y;
  int col = cb*32 + (threadIdx.x & 31);
  int rg  = threadIdx.x >> 5;
  int k0  = ks*256;
  for (int idx = threadIdx.x; idx < B*256; idx += 256){
    int r = idx >> 8, k = idx & 255;
    xs[r][k] = g_t[r*HID + k0 + k];
  }
  __syncthreads();
  float a0=0.f, a1=0.f, a2=0.f, a3=0.f;
  const float* wp = Wo + (size_t)k0*HID + col;
  #pragma unroll 4
  for (int k = 0; k < 256; k++){
    float w = wp[(size_t)k*HID];
    a0 += xs[rg*4+0][k]*w;
    a1 += xs[rg*4+1][k]*w;
    a2 += xs[rg*4+2][k]*w;
    a3 += xs[rg*4+3][k]*w;
  }
  float* op = g_out_part[ks];
  op[(rg*4+0)*HID + col] = a0;
  op[(rg*4+1)*HID + col] = a1;
  op[(rg*4+2)*HID + col] = a2;
  op[(rg*4+3)*HID + col] = a3;
}

// ---------------- sum split-K partials into final output ----------------
__global__ void k_sum(float* __restrict__ out){
  for (int i = blockIdx.x*blockDim.x + threadIdx.x; i < B*HID; i += gridDim.x*blockDim.x){
    float s = 0.f;
    #pragma unroll
    for (int ks = 0; ks < KSO; ks++) s += g_out_part[ks][i];
    out[i] = s;
  }
}

extern "C" void kernel_launch(void* const* d_in, const int* in_sizes, int n_in,
                              void* d_out, int out_size){
  const float* q   = (const float*)d_in[0];
  const float* kc  = (const float*)d_in[1];
  const float* kpe = (const float*)d_in[2];
  const float* kvc = (const float*)d_in[3];
  const float* Wq  = (const float*)d_in[4];
  const float* WK  = (const float*)d_in[5];
  const float* WV  = (const float*)d_in[6];
  const float* Wo  = (const float*)d_in[7];
  const int*  lens = (const int*)d_in[8];

  k_reset<<<1, 32>>>();
  k_amax<<<256, 256>>>(WK, WV);
  k_quant<<<1024, 256>>>(WK, WV);
  k_qp<<<dim3(96, KSQP), 256>>>(q, Wq);
  k_qf<<<dim3(H, B), 128>>>(kc, kpe, lens);
  k_attn<<<dim3(NCHUNK, B), 256>>>(kvc, lens);
  k_combine<<<dim3(H, B), 128>>>();
  k_out<<<dim3(64, KSO), 256>>>(Wo);
  k_sum<<<64, 256>>>((float*)d_out);
}

// round 3
// speedup vs baseline: 1.3101x; 1.3101x over previous
#include <cuda_runtime.h>
#include <cuda_fp8.h>
#include <math.h>

#define B 32
#define S 4096
#define H 16
#define KV_LORA 512
#define NOPE 128
#define ROPE 64
#define QKD 192
#define VD 128
#define QIN 1536
#define HID 2048
#define DKV 576
#define NQ (H*QKD)
#define SCALEF 0.07216878364870323f

#define NCHUNK 16
#define CHUNK 256
#define TILE 16
#define KSQ 24     // split-K for q-proj (64 k each)
#define KSO 32     // split-K for out-proj (64 k each)
#define VSPLIT 4   // split-C for V apply

// ---------------- device scratch ----------------
static __device__ unsigned g_amax[2];
static __device__ float g_WKd[H*KV_LORA*NOPE];
static __device__ float g_WVd[H*VD*KV_LORA];
static __device__ float g_qp_part[KSQ][B*NQ];
static __device__ float g_qn[B*H*NOPE];          // compact q_nope
static __device__ float g_qf[B*H*DKV];           // pre-scaled by SCALEF
static __device__ float g_newkv[B*DKV];
static __device__ float g_m[B*H*NCHUNK];
static __device__ float g_l[B*H*NCHUNK];
static __device__ float g_opart[B*H*NCHUNK*KV_LORA];
static __device__ float g_o[B*H*KV_LORA];
static __device__ float g_t_part[VSPLIT][B*HID];
static __device__ float g_out_part[KSO][B*HID];

__global__ void k_reset(){
  if (threadIdx.x < 2) g_amax[threadIdx.x] = 0u;
}

__global__ void k_amax(const float* __restrict__ WK, const float* __restrict__ WV){
  const int N = H*KV_LORA*NOPE;
  float m0 = 0.f, m1 = 0.f;
  for (int i = blockIdx.x*blockDim.x + threadIdx.x; i < N; i += gridDim.x*blockDim.x){
    m0 = fmaxf(m0, fabsf(WK[i]));
    m1 = fmaxf(m1, fabsf(WV[i]));
  }
  #pragma unroll
  for (int off = 16; off; off >>= 1){
    m0 = fmaxf(m0, __shfl_xor_sync(0xffffffffu, m0, off));
    m1 = fmaxf(m1, __shfl_xor_sync(0xffffffffu, m1, off));
  }
  __shared__ float s0[8], s1[8];
  int w = threadIdx.x >> 5;
  if ((threadIdx.x & 31) == 0){ s0[w] = m0; s1[w] = m1; }
  __syncthreads();
  if (threadIdx.x == 0){
    #pragma unroll
    for (int i = 1; i < 8; i++){ m0 = fmaxf(m0, s0[i]); m1 = fmaxf(m1, s1[i]); }
    atomicMax(&g_amax[0], __float_as_uint(m0));
    atomicMax(&g_amax[1], __float_as_uint(m1));
  }
}

__global__ void k_quant(const float* __restrict__ WK, const float* __restrict__ WV){
  const int N = H*KV_LORA*NOPE;
  float aK = fmaxf(__uint_as_float(g_amax[0]), 1e-10f);
  float aV = fmaxf(__uint_as_float(g_amax[1]), 1e-10f);
  float sK = 448.f / aK, sV = 448.f / aV;
  for (int i = blockIdx.x*blockDim.x + threadIdx.x; i < N; i += gridDim.x*blockDim.x){
    float x = fminf(fmaxf(WK[i]*sK, -448.f), 448.f);
    __nv_fp8_storage_t f8 = __nv_cvt_float_to_fp8(x, __NV_SATFINITE, __NV_E4M3);
    g_WKd[i] = __half2float(__half(__nv_cvt_fp8_to_halfraw(f8, __NV_E4M3))) / sK;
    float y = fminf(fmaxf(WV[i]*sV, -448.f), 448.f);
    __nv_fp8_storage_t g8 = __nv_cvt_float_to_fp8(y, __NV_SATFINITE, __NV_E4M3);
    g_WVd[i] = __half2float(__half(__nv_cvt_fp8_to_halfraw(g8, __NV_E4M3))) / sV;
  }
}

// ---------------- qp = q @ Wq, float4 cols, 8 rows x 4 cols per thread ----------------
__global__ void __launch_bounds__(256) k_qp(const float* __restrict__ q,
                                            const float* __restrict__ Wq){
  __shared__ float xs[B][64];
  int cb = blockIdx.x, ks = blockIdx.y;
  int tx = threadIdx.x & 63;         // float4 col within 64
  int ty = threadIdx.x >> 6;         // row group (8 rows)
  int k0 = ks*64;
  for (int idx = threadIdx.x; idx < B*64; idx += 256){
    int r = idx >> 6, k = idx & 63;
    xs[r][k] = q[r*QIN + k0 + k];
  }
  __syncthreads();
  float4 acc[8];
  #pragma unroll
  for (int i = 0; i < 8; i++) acc[i] = make_float4(0.f,0.f,0.f,0.f);
  const float4* Wq4 = (const float4*)Wq;
  size_t wbase = (size_t)k0*(NQ/4) + cb*64 + tx;
  #pragma unroll 4
  for (int k = 0; k < 64; k++){
    float4 w = Wq4[wbase + (size_t)k*(NQ/4)];
    #pragma unroll
    for (int i = 0; i < 8; i++){
      float xv = xs[ty*8 + i][k];
      acc[i].x += xv*w.x; acc[i].y += xv*w.y; acc[i].z += xv*w.z; acc[i].w += xv*w.w;
    }
  }
  float4* op = (float4*)g_qp_part[ks];
  #pragma unroll
  for (int i = 0; i < 8; i++)
    op[(size_t)(ty*8 + i)*(NQ/4) + cb*64 + tx] = acc[i];
}

// ---------------- reduce qp partials, rope, build q_nope + qf-rope + new_kv ----------------
__global__ void __launch_bounds__(256) k_qred(const float* __restrict__ kc,
                                              const float* __restrict__ kpe,
                                              const int* __restrict__ kv_lens){
  int b = blockIdx.x;
  int tid = threadIdx.x;
  __shared__ float qs[NQ];
  #pragma unroll
  for (int j = 0; j < NQ/256; j++){
    int col = tid + j*256;
    float s = 0.f;
    #pragma unroll
    for (int ks = 0; ks < KSQ; ks++) s += g_qp_part[ks][b*NQ + col];
    qs[col] = s;
  }
  __syncthreads();
  // compact nope
  #pragma unroll
  for (int j = 0; j < (H*NOPE)/256; j++){
    int idx = tid + j*256;
    int h = idx >> 7, d = idx & 127;
    g_qn[(b*H + h)*NOPE + d] = qs[h*QKD + d];
  }
  int pos = kv_lens[b];
  // rope for q_pe (all heads), pre-scaled
  #pragma unroll
  for (int it = 0; it < 2; it++){
    int idx = tid + it*256;
    int h = idx >> 5, i = idx & 31;
    double e   = (2.0*i)/64.0;
    double inv = exp(-e * 9.210340371976184);
    double ang = (double)pos * inv;
    float cs = (float)cos(ang), sn = (float)sin(ang);
    float x1 = qs[h*QKD + NOPE + i], x2 = qs[h*QKD + NOPE + 32 + i];
    float* qf = g_qf + (size_t)(b*H + h)*DKV;
    qf[KV_LORA + i]      = (x1*cs - x2*sn)*SCALEF;
    qf[KV_LORA + 32 + i] = (x2*cs + x1*sn)*SCALEF;
  }
  // new_kv
  #pragma unroll
  for (int it = 0; it < 2; it++){
    int c = tid + it*256;
    g_newkv[b*DKV + c] = kc[b*KV_LORA + c];
  }
  if (tid < 32){
    int i = tid;
    double e   = (2.0*i)/64.0;
    double inv = exp(-e * 9.210340371976184);
    double ang = (double)pos * inv;
    float cs = (float)cos(ang), sn = (float)sin(ang);
    float k1 = kpe[b*ROPE + i], k2 = kpe[b*ROPE + 32 + i];
    g_newkv[b*DKV + KV_LORA + i]      = k1*cs - k2*sn;
    g_newkv[b*DKV + KV_LORA + 32 + i] = k2*cs + k1*sn;
  }
}

// ---------------- ql_nope = q_nope @ W_Kd^T, weights read once, pre-scaled ----------------
__global__ void __launch_bounds__(256) k_qk(){
  int h = blockIdx.y, c0 = blockIdx.x*128;
  int tid = threadIdx.x;
  int cc = tid & 127, rg = tid >> 7;
  __shared__ float qn_s[B][NOPE];
  __shared__ float ws[128][33];
  for (int idx = tid; idx < B*NOPE; idx += 256){
    int r = idx >> 7, d = idx & 127;
    qn_s[r][d] = g_qn[(r*H + h)*NOPE + d];
  }
  float acc[16];
  #pragma unroll
  for (int i = 0; i < 16; i++) acc[i] = 0.f;
  for (int db = 0; db < NOPE; db += 32){
    __syncthreads();
    #pragma unroll
    for (int it = 0; it < 16; it++){
      int idx = tid + it*256;
      int c = idx >> 5, d = idx & 31;
      ws[c][d] = g_WKd[(size_t)(h*KV_LORA + c0 + c)*NOPE + db + d];
    }
    __syncthreads();
    #pragma unroll
    for (int d = 0; d < 32; d++){
      float w = ws[cc][d];
      #pragma unroll
      for (int r = 0; r < 16; r++)
        acc[r] += qn_s[rg*16 + r][db + d]*w;
    }
  }
  #pragma unroll
  for (int r = 0; r < 16; r++){
    int b = rg*16 + r;
    g_qf[(size_t)(b*H + h)*DKV + c0 + cc] = acc[r]*SCALEF;
  }
}

// ---------------- split-KV flash attention: 2 heads/warp, scores in registers ----------------
__global__ void __launch_bounds__(256) k_attn(const float* __restrict__ kv_cache,
                                              const int* __restrict__ kv_lens){
  int chunk = blockIdx.x, b = blockIdx.y;
  int warp = threadIdx.x >> 5, lane = threadIdx.x & 31;
  int h0 = warp*2;
  int len = kv_lens[b];
  int s_begin = chunk*CHUNK;
  int s_end = min(s_begin + CHUNK, len + 1);

  __shared__ float kvs[TILE][DKV];

  float2 qr0[9], qr1[9];
  const float2* qf0 = (const float2*)(g_qf + (size_t)(b*H + h0)*DKV);
  const float2* qf1 = (const float2*)(g_qf + (size_t)(b*H + h0 + 1)*DKV);
  #pragma unroll
  for (int j = 0; j < 9; j++){ qr0[j] = qf0[j*32 + lane]; qr1[j] = qf1[j*32 + lane]; }

  float2 a0[8], a1[8];
  #pragma unroll
  for (int j = 0; j < 8; j++){ a0[j] = make_float2(0.f,0.f); a1[j] = make_float2(0.f,0.f); }
  float m0 = -INFINITY, m1 = -INFINITY, l0 = 0.f, l1 = 0.f;

  for (int t0 = s_begin; t0 < s_end; t0 += TILE){
    int rows = min(TILE, s_end - t0);
    __syncthreads();
    for (int idx = threadIdx.x; idx < rows*(DKV/4); idx += 256){
      int r  = idx / (DKV/4);
      int c4 = idx - r*(DKV/4);
      int s  = t0 + r;
      const float4* src = (s == len) ? (const float4*)(g_newkv + b*DKV)
                                     : (const float4*)(kv_cache + ((size_t)b*S + s)*DKV);
      ((float4*)kvs[r])[c4] = src[c4];
    }
    __syncthreads();

    // scores: qf is pre-scaled; capture row score in lane==r
    float s0 = -INFINITY, s1 = -INFINITY;
    for (int r = 0; r < rows; r++){
      const float2* row = (const float2*)kvs[r];
      float x0 = 0.f, x1 = 0.f;
      #pragma unroll
      for (int j = 0; j < 9; j++){
        float2 kv = row[j*32 + lane];
        x0 += qr0[j].x*kv.x + qr0[j].y*kv.y;
        x1 += qr1[j].x*kv.x + qr1[j].y*kv.y;
      }
      #pragma unroll
      for (int off = 16; off; off >>= 1){
        x0 += __shfl_xor_sync(0xffffffffu, x0, off);
        x1 += __shfl_xor_sync(0xffffffffu, x1, off);
      }
      if (lane == r){ s0 = x0; s1 = x1; }
    }

    // tile max (butterfly)
    float tm0 = s0, tm1 = s1;
    #pragma unroll
    for (int off = 16; off; off >>= 1){
      tm0 = fmaxf(tm0, __shfl_xor_sync(0xffffffffu, tm0, off));
      tm1 = fmaxf(tm1, __shfl_xor_sync(0xffffffffu, tm1, off));
    }
    float nm0 = fmaxf(m0, tm0), nm1 = fmaxf(m1, tm1);
    float cf0 = __expf(m0 - nm0), cf1 = __expf(m1 - nm1);
    m0 = nm0; m1 = nm1;

    float p0 = __expf(s0 - nm0), p1 = __expf(s1 - nm1);   // 0 for lanes >= rows
    float sp0 = p0, sp1 = p1;
    #pragma unroll
    for (int off = 16; off; off >>= 1){
      sp0 += __shfl_xor_sync(0xffffffffu, sp0, off);
      sp1 += __shfl_xor_sync(0xffffffffu, sp1, off);
    }
    l0 = l0*cf0 + sp0; l1 = l1*cf1 + sp1;

    #pragma unroll
    for (int j = 0; j < 8; j++){
      a0[j].x *= cf0; a0[j].y *= cf0;
      a1[j].x *= cf1; a1[j].y *= cf1;
    }
    for (int r = 0; r < rows; r++){
      float pp0 = __shfl_sync(0xffffffffu, p0, r);
      float pp1 = __shfl_sync(0xffffffffu, p1, r);
      const float2* row = (const float2*)kvs[r];
      #pragma unroll
      for (int j = 0; j < 8; j++){
        float2 kv = row[j*32 + lane];
        a0[j].x += pp0*kv.x; a0[j].y += pp0*kv.y;
        a1[j].x += pp1*kv.x; a1[j].y += pp1*kv.y;
      }
    }
  }

  int base = (b*H + h0)*NCHUNK + chunk;
  if (lane == 0){
    g_m[base] = m0; g_l[base] = l0;
    g_m[base + NCHUNK] = m1; g_l[base + NCHUNK] = l1;
  }
  float2* o0 = (float2*)g_opart + (size_t)base*(KV_LORA/2);
  float2* o1 = (float2*)g_opart + (size_t)(base + NCHUNK)*(KV_LORA/2);
  #pragma unroll
  for (int j = 0; j < 8; j++){
    o0[j*32 + lane] = a0[j];
    o1[j*32 + lane] = a1[j];
  }
}

// ---------------- combine split-softmax partials (bandwidth only) ----------------
__global__ void __launch_bounds__(128) k_comb(){
  int h = blockIdx.x, b = blockIdx.y;
  int tid = threadIdx.x;
  int base = (b*H + h)*NCHUNK;
  float mstar = -INFINITY;
  #pragma unroll
  for (int c = 0; c < NCHUNK; c++) mstar = fmaxf(mstar, g_m[base + c]);
  float ecf[NCHUNK];
  float lstar = 0.f;
  #pragma unroll
  for (int c = 0; c < NCHUNK; c++){
    float e = expf(g_m[base + c] - mstar);
    ecf[c] = e;
    lstar += e * g_l[base + c];
  }
  float inv_l = 1.f / lstar;
  #pragma unroll
  for (int j = 0; j < KV_LORA/128; j++){
    int d = tid + j*128;
    float s = 0.f;
    #pragma unroll
    for (int c = 0; c < NCHUNK; c++)
      s += ecf[c] * g_opart[(size_t)(base + c)*KV_LORA + d];
    g_o[(size_t)(b*H + h)*KV_LORA + d] = s * inv_l;
  }
}

// ---------------- t = o @ W_Vd^T, weights read once, split-C ----------------
__global__ void __launch_bounds__(256) k_v(){
  int cs = blockIdx.x, h = blockIdx.y;
  int tid = threadIdx.x;
  int vv = tid & 127, rg = tid >> 7;
  __shared__ float ws[128][33];
  __shared__ float os[B][32];
  float acc[16];
  #pragma unroll
  for (int i = 0; i < 16; i++) acc[i] = 0.f;
  for (int cb = 0; cb < 128; cb += 32){
    int c0 = cs*128 + cb;
    __syncthreads();
    #pragma unroll
    for (int it = 0; it < 16; it++){
      int idx = tid + it*256;
      int v = idx >> 5, d = idx & 31;
      ws[v][d] = g_WVd[(size_t)(h*VD + v)*KV_LORA + c0 + d];
    }
    #pragma unroll
    for (int it = 0; it < 4; it++){
      int idx = tid + it*256;
      int r = idx >> 5, d = idx & 31;
      os[r][d] = g_o[(size_t)(r*H + h)*KV_LORA + c0 + d];
    }
    __syncthreads();
    #pragma unroll
    for (int d = 0; d < 32; d++){
      float w = ws[vv][d];
      #pragma unroll
      for (int r = 0; r < 16; r++)
        acc[r] += os[rg*16 + r][d]*w;
    }
  }
  #pragma unroll
  for (int r = 0; r < 16; r++){
    int b = rg*16 + r;
    g_t_part[cs][b*HID + h*VD + vv] = acc[r];
  }
}

// ---------------- out = t @ Wo, float4 cols, split-K ----------------
__global__ void __launch_bounds__(256) k_out(const float* __restrict__ Wo){
  __shared__ float xs[B][64];
  int cb = blockIdx.x, ks = blockIdx.y;
  int tx = threadIdx.x & 63;
  int ty = threadIdx.x >> 6;
  int k0 = ks*64;
  for (int idx = threadIdx.x; idx < B*64; idx += 256){
    int r = idx >> 6, k = idx & 63;
    float s = 0.f;
    #pragma unroll
    for (int p = 0; p < VSPLIT; p++) s += g_t_part[p][r*HID + k0 + k];
    xs[r][k] = s;
  }
  __syncthreads();
  float4 acc[8];
  #pragma unroll
  for (int i = 0; i < 8; i++) acc[i] = make_float4(0.f,0.f,0.f,0.f);
  const float4* Wo4 = (const float4*)Wo;
  size_t wbase = (size_t)k0*(HID/4) + cb*64 + tx;
  #pragma unroll 4
  for (int k = 0; k < 64; k++){
    float4 w = Wo4[wbase + (size_t)k*(HID/4)];
    #pragma unroll
    for (int i = 0; i < 8; i++){
      float xv = xs[ty*8 + i][k];
      acc[i].x += xv*w.x; acc[i].y += xv*w.y; acc[i].z += xv*w.z; acc[i].w += xv*w.w;
    }
  }
  float4* op = (float4*)g_out_part[ks];
  #pragma unroll
  for (int i = 0; i < 8; i++)
    op[(size_t)(ty*8 + i)*(HID/4) + cb*64 + tx] = acc[i];
}

__global__ void k_sum(float* __restrict__ out){
  int i = blockIdx.x*blockDim.x + threadIdx.x;
  if (i < B*HID){
    float s = 0.f;
    #pragma unroll
    for (int ks = 0; ks < KSO; ks++) s += g_out_part[ks][i];
    out[i] = s;
  }
}

extern "C" void kernel_launch(void* const* d_in, const int* in_sizes, int n_in,
                              void* d_out, int out_size){
  const float* q   = (const float*)d_in[0];
  const float* kc  = (const float*)d_in[1];
  const float* kpe = (const float*)d_in[2];
  const float* kvc = (const float*)d_in[3];
  const float* Wq  = (const float*)d_in[4];
  const float* WK  = (const float*)d_in[5];
  const float* WV  = (const float*)d_in[6];
  const float* Wo  = (const float*)d_in[7];
  const int*  lens = (const int*)d_in[8];

  k_reset<<<1, 32>>>();
  k_amax<<<256, 256>>>(WK, WV);
  k_quant<<<1024, 256>>>(WK, WV);
  k_qp<<<dim3(NQ/256, KSQ), 256>>>(q, Wq);
  k_qred<<<B, 256>>>(kc, kpe, lens);
  k_qk<<<dim3(KV_LORA/128, H), 256>>>();
  k_attn<<<dim3(NCHUNK, B), 256>>>(kvc, lens);
  k_comb<<<dim3(H, B), 128>>>();
  k_v<<<dim3(VSPLIT, H), 256>>>();
  k_out<<<dim3(HID/256, KSO), 256>>>(Wo);
  k_sum<<<256, 256>>>((float*)d_out);
}

// round 4
// speedup vs baseline: 1.3347x; 1.0188x over previous
#include <cuda_runtime.h>
#include <cuda_fp8.h>
#include <math.h>

#define B 32
#define S 4096
#define H 16
#define KV_LORA 512
#define NOPE 128
#define ROPE 64
#define QKD 192
#define VD 128
#define QIN 1536
#define HID 2048
#define DKV 576
#define NQ (H*QKD)
#define SCALEF 0.07216878364870323f

#define NCHUNK 16
#define CHUNK 256
#define TILE 16
#define KSQ 16     // split-K for q-proj (96 k each)
#define KSO 16     // split-K for out-proj (128 k each)
#define VSPLIT 4

typedef unsigned long long ull;

// ---------------- packed f32x2 helpers ----------------
__device__ __forceinline__ ull pk2(float x, float y){
  ull r; asm("mov.b64 %0, {%1, %2};" : "=l"(r) : "f"(x), "f"(y)); return r;
}
__device__ __forceinline__ float2 upk2(ull v){
  float2 r; asm("mov.b64 {%0, %1}, %2;" : "=f"(r.x), "=f"(r.y) : "l"(v)); return r;
}
__device__ __forceinline__ ull ffma2(ull a, ull b, ull c){
  ull d; asm("fma.rn.f32x2 %0, %1, %2, %3;" : "=l"(d) : "l"(a), "l"(b), "l"(c)); return d;
}
__device__ __forceinline__ ull fmul2(ull a, ull b){
  ull d; asm("mul.rn.f32x2 %0, %1, %2;" : "=l"(d) : "l"(a), "l"(b)); return d;
}
__device__ __forceinline__ ull fadd2(ull a, ull b){
  ull d; asm("add.rn.f32x2 %0, %1, %2;" : "=l"(d) : "l"(a), "l"(b)); return d;
}

// ---------------- device scratch ----------------
static __device__ unsigned g_amax[2];
static __device__ float g_WKd[H*KV_LORA*NOPE];
static __device__ float g_WVd[H*VD*KV_LORA];
static __device__ float g_qp_part[KSQ][B*NQ];
static __device__ float g_qn[B*H*NOPE];
static __device__ float g_qf[B*H*DKV];           // pre-scaled by SCALEF
static __device__ float g_newkv[B*DKV];
static __device__ float g_m[B*H*NCHUNK];
static __device__ float g_l[B*H*NCHUNK];
static __device__ float g_opart[B*H*NCHUNK*KV_LORA];
static __device__ float g_o[B*H*KV_LORA];
static __device__ float g_t_part[VSPLIT][B*HID];
static __device__ float g_out_part[KSO][B*HID];

__global__ void k_reset(){
  if (threadIdx.x < 2) g_amax[threadIdx.x] = 0u;
}

__global__ void k_amax(const float* __restrict__ WK, const float* __restrict__ WV){
  const int N4 = (H*KV_LORA*NOPE)/4;
  const float4* WK4 = (const float4*)WK;
  const float4* WV4 = (const float4*)WV;
  float m0 = 0.f, m1 = 0.f;
  for (int i = blockIdx.x*blockDim.x + threadIdx.x; i < N4; i += gridDim.x*blockDim.x){
    float4 a = WK4[i], b = WV4[i];
    m0 = fmaxf(m0, fmaxf(fmaxf(fabsf(a.x),fabsf(a.y)), fmaxf(fabsf(a.z),fabsf(a.w))));
    m1 = fmaxf(m1, fmaxf(fmaxf(fabsf(b.x),fabsf(b.y)), fmaxf(fabsf(b.z),fabsf(b.w))));
  }
  #pragma unroll
  for (int off = 16; off; off >>= 1){
    m0 = fmaxf(m0, __shfl_xor_sync(0xffffffffu, m0, off));
    m1 = fmaxf(m1, __shfl_xor_sync(0xffffffffu, m1, off));
  }
  __shared__ float s0[8], s1[8];
  int w = threadIdx.x >> 5;
  if ((threadIdx.x & 31) == 0){ s0[w] = m0; s1[w] = m1; }
  __syncthreads();
  if (threadIdx.x == 0){
    #pragma unroll
    for (int i = 1; i < 8; i++){ m0 = fmaxf(m0, s0[i]); m1 = fmaxf(m1, s1[i]); }
    atomicMax(&g_amax[0], __float_as_uint(m0));
    atomicMax(&g_amax[1], __float_as_uint(m1));
  }
}

__device__ __forceinline__ float fq8(float v, float s){
  float x = fminf(fmaxf(v*s, -448.f), 448.f);
  __nv_fp8_storage_t f8 = __nv_cvt_float_to_fp8(x, __NV_SATFINITE, __NV_E4M3);
  return __half2float(__half(__nv_cvt_fp8_to_halfraw(f8, __NV_E4M3))) / s;
}

__global__ void k_quant(const float* __restrict__ WK, const float* __restrict__ WV){
  const int N4 = (H*KV_LORA*NOPE)/4;
  float aK = fmaxf(__uint_as_float(g_amax[0]), 1e-10f);
  float aV = fmaxf(__uint_as_float(g_amax[1]), 1e-10f);
  float sK = 448.f / aK, sV = 448.f / aV;
  const float4* WK4 = (const float4*)WK;
  const float4* WV4 = (const float4*)WV;
  float4* OK4 = (float4*)g_WKd;
  float4* OV4 = (float4*)g_WVd;
  for (int i = blockIdx.x*blockDim.x + threadIdx.x; i < N4; i += gridDim.x*blockDim.x){
    float4 a = WK4[i];
    OK4[i] = make_float4(fq8(a.x,sK), fq8(a.y,sK), fq8(a.z,sK), fq8(a.w,sK));
    float4 b = WV4[i];
    OV4[i] = make_float4(fq8(b.x,sV), fq8(b.y,sV), fq8(b.z,sV), fq8(b.w,sV));
  }
}

// ---------------- qp = q @ Wq: 4 rows x float4 per thread, HBM-bound ----------------
__global__ void __launch_bounds__(256) k_qp(const float* __restrict__ q,
                                            const float* __restrict__ Wq){
  __shared__ float xs[B][96];
  int cb = blockIdx.x, ks = blockIdx.y;
  int tx = threadIdx.x & 31;         // float4 col
  int ty = threadIdx.x >> 5;         // row group (4 rows)
  int k0 = ks*96;
  const float4* q4 = (const float4*)q;
  for (int idx = threadIdx.x; idx < B*24; idx += 256){
    int r = idx / 24, c4 = idx % 24;
    float4 v = q4[r*(QIN/4) + k0/4 + c4];
    xs[r][c4*4+0]=v.x; xs[r][c4*4+1]=v.y; xs[r][c4*4+2]=v.z; xs[r][c4*4+3]=v.w;
  }
  __syncthreads();
  float4 acc[4];
  #pragma unroll
  for (int i = 0; i < 4; i++) acc[i] = make_float4(0.f,0.f,0.f,0.f);
  const float4* wp = (const float4*)Wq + (size_t)k0*(NQ/4) + cb*32 + tx;
  #pragma unroll 8
  for (int k = 0; k < 96; k++){
    float4 w = wp[(size_t)k*(NQ/4)];
    #pragma unroll
    for (int i = 0; i < 4; i++){
      float xv = xs[ty*4 + i][k];
      acc[i].x += xv*w.x; acc[i].y += xv*w.y; acc[i].z += xv*w.z; acc[i].w += xv*w.w;
    }
  }
  float4* op = (float4*)g_qp_part[ks];
  #pragma unroll
  for (int i = 0; i < 4; i++)
    op[(size_t)(ty*4 + i)*(NQ/4) + cb*32 + tx] = acc[i];
}

// ---------------- reduce qp partials, rope, q_nope + qf-rope + new_kv ----------------
__global__ void __launch_bounds__(256) k_qred(const float* __restrict__ kc,
                                              const float* __restrict__ kpe,
                                              const int* __restrict__ kv_lens){
  int b = blockIdx.x;
  int tid = threadIdx.x;
  __shared__ float qs[NQ];
  #pragma unroll
  for (int j = 0; j < NQ/256; j++){
    int col = tid + j*256;
    float s = 0.f;
    #pragma unroll
    for (int ks = 0; ks < KSQ; ks++) s += g_qp_part[ks][b*NQ + col];
    qs[col] = s;
  }
  __syncthreads();
  #pragma unroll
  for (int j = 0; j < (H*NOPE)/256; j++){
    int idx = tid + j*256;
    int h = idx >> 7, d = idx & 127;
    g_qn[(b*H + h)*NOPE + d] = qs[h*QKD + d];
  }
  int pos = kv_lens[b];
  #pragma unroll
  for (int it = 0; it < 2; it++){
    int idx = tid + it*256;
    int h = idx >> 5, i = idx & 31;
    double e   = (2.0*i)/64.0;
    double inv = exp(-e * 9.210340371976184);
    double ang = (double)pos * inv;
    float cs = (float)cos(ang), sn = (float)sin(ang);
    float x1 = qs[h*QKD + NOPE + i], x2 = qs[h*QKD + NOPE + 32 + i];
    float* qf = g_qf + (size_t)(b*H + h)*DKV;
    qf[KV_LORA + i]      = (x1*cs - x2*sn)*SCALEF;
    qf[KV_LORA + 32 + i] = (x2*cs + x1*sn)*SCALEF;
  }
  #pragma unroll
  for (int it = 0; it < 2; it++){
    int c = tid + it*256;
    g_newkv[b*DKV + c] = kc[b*KV_LORA + c];
  }
  if (tid < 32){
    int i = tid;
    double e   = (2.0*i)/64.0;
    double inv = exp(-e * 9.210340371976184);
    double ang = (double)pos * inv;
    float cs = (float)cos(ang), sn = (float)sin(ang);
    float k1 = kpe[b*ROPE + i], k2 = kpe[b*ROPE + 32 + i];
    g_newkv[b*DKV + KV_LORA + i]      = k1*cs - k2*sn;
    g_newkv[b*DKV + KV_LORA + 32 + i] = k2*cs + k1*sn;
  }
}

// ---------------- ql_nope = q_nope @ W_Kd^T ----------------
__global__ void __launch_bounds__(256) k_qk(){
  int h = blockIdx.y, c0 = blockIdx.x*128;
  int tid = threadIdx.x;
  int cc = tid & 127, rg = tid >> 7;
  __shared__ float qn_s[B][NOPE];
  __shared__ float ws[128][33];
  for (int idx = tid; idx < B*NOPE; idx += 256){
    int r = idx >> 7, d = idx & 127;
    qn_s[r][d] = g_qn[(r*H + h)*NOPE + d];
  }
  float acc[16];
  #pragma unroll
  for (int i = 0; i < 16; i++) acc[i] = 0.f;
  for (int db = 0; db < NOPE; db += 32){
    __syncthreads();
    #pragma unroll
    for (int it = 0; it < 16; it++){
      int idx = tid + it*256;
      int c = idx >> 5, d = idx & 31;
      ws[c][d] = g_WKd[(size_t)(h*KV_LORA + c0 + c)*NOPE + db + d];
    }
    __syncthreads();
    #pragma unroll
    for (int d = 0; d < 32; d++){
      float w = ws[cc][d];
      #pragma unroll
      for (int r = 0; r < 16; r++)
        acc[r] += qn_s[rg*16 + r][db + d]*w;
    }
  }
  #pragma unroll
  for (int r = 0; r < 16; r++){
    int b = rg*16 + r;
    g_qf[(size_t)(b*H + h)*DKV + c0 + cc] = acc[r]*SCALEF;
  }
}

// ---------------- flash attention: 4 heads/warp x half-tile rows, f32x2 FMA ----------------
__global__ void __launch_bounds__(256) k_attn(const float* __restrict__ kv_cache,
                                              const int* __restrict__ kv_lens){
  int chunk = blockIdx.x, b = blockIdx.y;
  int warp = threadIdx.x >> 5, lane = threadIdx.x & 31;
  int wg = warp & 3;            // head group: heads wg*4 .. wg*4+3
  int rh = warp >> 2;           // row half: rows rh*8 .. rh*8+7 of tile
  int hg = wg*4;
  int len = kv_lens[b];
  int s_begin = chunk*CHUNK;
  int s_end = min(s_begin + CHUNK, len + 1);

  __shared__ float kvs[TILE][DKV];      // 36.8 KB, reused as merge buffer
  __shared__ float mlx[4][4][2];        // [wg][head][m,l] from rh==1 warps

  // q packed (pre-scaled by SCALEF)
  ull q2[4][9];
  #pragma unroll
  for (int h = 0; h < 4; h++){
    const ull* qf = (const ull*)(g_qf + (size_t)(b*H + hg + h)*DKV);
    #pragma unroll
    for (int j = 0; j < 9; j++) q2[h][j] = qf[j*32 + lane];
  }

  ull acc[4][8];
  #pragma unroll
  for (int h = 0; h < 4; h++)
    #pragma unroll
    for (int j = 0; j < 8; j++) acc[h][j] = 0ull;
  float m[4], l[4];
  #pragma unroll
  for (int h = 0; h < 4; h++){ m[h] = -1e30f; l[h] = 0.f; }

  for (int t0 = s_begin; t0 < s_end; t0 += TILE){
    int rows = min(TILE, s_end - t0);
    __syncthreads();
    for (int idx = threadIdx.x; idx < rows*144; idx += 256){
      int r  = idx / 144;
      int c4 = idx - r*144;
      int s  = t0 + r;
      const float4* src = (s == len) ? (const float4*)(g_newkv + b*DKV)
                                     : (const float4*)(kv_cache + ((size_t)b*S + s)*DKV);
      ((float4*)kvs[r])[c4] = src[c4];
    }
    __syncthreads();

    int r0 = rh*8;
    int rows_w = min(8, rows - r0);
    if (rows_w > 0){
      // ---- scores ----
      float sc[4];
      #pragma unroll
      for (int h = 0; h < 4; h++) sc[h] = -1e30f;
      for (int r = 0; r < rows_w; r++){
        const ull* row = (const ull*)kvs[r0 + r];
        ull sa0 = 0, sa1 = 0, sa2 = 0, sa3 = 0;
        #pragma unroll
        for (int j = 0; j < 9; j++){
          ull kv = row[j*32 + lane];
          sa0 = ffma2(q2[0][j], kv, sa0);
          sa1 = ffma2(q2[1][j], kv, sa1);
          sa2 = ffma2(q2[2][j], kv, sa2);
          sa3 = ffma2(q2[3][j], kv, sa3);
        }
        float2 v0 = upk2(sa0), v1 = upk2(sa1), v2 = upk2(sa2), v3 = upk2(sa3);
        float x0 = v0.x + v0.y, x1 = v1.x + v1.y, x2 = v2.x + v2.y, x3 = v3.x + v3.y;
        #pragma unroll
        for (int off = 16; off; off >>= 1){
          x0 += __shfl_xor_sync(0xffffffffu, x0, off);
          x1 += __shfl_xor_sync(0xffffffffu, x1, off);
          x2 += __shfl_xor_sync(0xffffffffu, x2, off);
          x3 += __shfl_xor_sync(0xffffffffu, x3, off);
        }
        if (lane == r){ sc[0]=x0; sc[1]=x1; sc[2]=x2; sc[3]=x3; }
      }

      // ---- online softmax update ----
      float p[4];
      #pragma unroll
      for (int h = 0; h < 4; h++){
        float tm = sc[h];
        #pragma unroll
        for (int off = 16; off; off >>= 1)
          tm = fmaxf(tm, __shfl_xor_sync(0xffffffffu, tm, off));
        float nm = fmaxf(m[h], tm);
        float cf = __expf(m[h] - nm);
        m[h] = nm;
        p[h] = __expf(sc[h] - nm);
        float sp = p[h];
        #pragma unroll
        for (int off = 16; off; off >>= 1)
          sp += __shfl_xor_sync(0xffffffffu, sp, off);
        l[h] = l[h]*cf + sp;
        ull c2 = pk2(cf, cf);
        #pragma unroll
        for (int j = 0; j < 8; j++) acc[h][j] = fmul2(acc[h][j], c2);
      }

      // ---- accumulate ----
      for (int r = 0; r < rows_w; r++){
        ull pp0 = pk2(__shfl_sync(0xffffffffu, p[0], r), __shfl_sync(0xffffffffu, p[0], r));
        ull pp1 = pk2(__shfl_sync(0xffffffffu, p[1], r), __shfl_sync(0xffffffffu, p[1], r));
        ull pp2 = pk2(__shfl_sync(0xffffffffu, p[2], r), __shfl_sync(0xffffffffu, p[2], r));
        ull pp3 = pk2(__shfl_sync(0xffffffffu, p[3], r), __shfl_sync(0xffffffffu, p[3], r));
        const ull* row = (const ull*)kvs[r0 + r];
        #pragma unroll
        for (int j = 0; j < 8; j++){
          ull kv = row[j*32 + lane];
          acc[0][j] = ffma2(pp0, kv, acc[0][j]);
          acc[1][j] = ffma2(pp1, kv, acc[1][j]);
          acc[2][j] = ffma2(pp2, kv, acc[2][j]);
          acc[3][j] = ffma2(pp3, kv, acc[3][j]);
        }
      }
    }
  }

  // ---- merge row-half warps and store partials ----
  __syncthreads();
  ull* bufu = (ull*)&kvs[0][0];
  if (rh == 1){
    #pragma unroll
    for (int h = 0; h < 4; h++){
      #pragma unroll
      for (int j = 0; j < 8; j++)
        bufu[(size_t)(hg + h)*256 + j*32 + lane] = acc[h][j];
    }
    if (lane == 0){
      #pragma unroll
      for (int h = 0; h < 4; h++){ mlx[wg][h][0] = m[h]; mlx[wg][h][1] = l[h]; }
    }
  }
  __syncthreads();
  if (rh == 0){
    #pragma unroll
    for (int h = 0; h < 4; h++){
      float mb = mlx[wg][h][0], lb = mlx[wg][h][1];
      float nm = fmaxf(m[h], mb);
      float ca = __expf(m[h] - nm), cb = __expf(mb - nm);
      float lm = l[h]*ca + lb*cb;
      ull ca2 = pk2(ca, ca), cb2 = pk2(cb, cb);
      int basep = (b*H + hg + h)*NCHUNK + chunk;
      if (lane == 0){ g_m[basep] = nm; g_l[basep] = lm; }
      ull* op = (ull*)g_opart + (size_t)basep*256;
      #pragma unroll
      for (int j = 0; j < 8; j++){
        ull v = fadd2(fmul2(acc[h][j], ca2),
                      fmul2(bufu[(size_t)(hg + h)*256 + j*32 + lane], cb2));
        op[j*32 + lane] = v;
      }
    }
  }
}

// ---------------- combine split-softmax partials ----------------
__global__ void __launch_bounds__(128) k_comb(){
  int h = blockIdx.x, b = blockIdx.y;
  int tid = threadIdx.x;
  int base = (b*H + h)*NCHUNK;
  float mstar = -1e30f;
  #pragma unroll
  for (int c = 0; c < NCHUNK; c++) mstar = fmaxf(mstar, g_m[base + c]);
  float ecf[NCHUNK];
  float lstar = 0.f;
  #pragma unroll
  for (int c = 0; c < NCHUNK; c++){
    float e = expf(g_m[base + c] - mstar);
    ecf[c] = e;
    lstar += e * g_l[base + c];
  }
  float inv_l = 1.f / lstar;
  #pragma unroll
  for (int j = 0; j < KV_LORA/128; j++){
    int d = tid + j*128;
    float s = 0.f;
    #pragma unroll
    for (int c = 0; c < NCHUNK; c++)
      s += ecf[c] * g_opart[(size_t)(base + c)*KV_LORA + d];
    g_o[(size_t)(b*H + h)*KV_LORA + d] = s * inv_l;
  }
}

// ---------------- t = o @ W_Vd^T ----------------
__global__ void __launch_bounds__(256) k_v(){
  int cs = blockIdx.x, h = blockIdx.y;
  int tid = threadIdx.x;
  int vv = tid & 127, rg = tid >> 7;
  __shared__ float ws[128][33];
  __shared__ float os[B][32];
  float acc[16];
  #pragma unroll
  for (int i = 0; i < 16; i++) acc[i] = 0.f;
  for (int cbk = 0; cbk < 128; cbk += 32){
    int c0 = cs*128 + cbk;
    __syncthreads();
    #pragma unroll
    for (int it = 0; it < 16; it++){
      int idx = tid + it*256;
      int v = idx >> 5, d = idx & 31;
      ws[v][d] = g_WVd[(size_t)(h*VD + v)*KV_LORA + c0 + d];
    }
    #pragma unroll
    for (int it = 0; it < 4; it++){
      int idx = tid + it*256;
      int r = idx >> 5, d = idx & 31;
      os[r][d] = g_o[(size_t)(r*H + h)*KV_LORA + c0 + d];
    }
    __syncthreads();
    #pragma unroll
    for (int d = 0; d < 32; d++){
      float w = ws[vv][d];
      #pragma unroll
      for (int r = 0; r < 16; r++)
        acc[r] += os[rg*16 + r][d]*w;
    }
  }
  #pragma unroll
  for (int r = 0; r < 16; r++){
    int b = rg*16 + r;
    g_t_part[cs][b*HID + h*VD + vv] = acc[r];
  }
}

// ---------------- out = t @ Wo ----------------
__global__ void __launch_bounds__(256) k_out(const float* __restrict__ Wo){
  __shared__ float xs[B][128];
  int cb = blockIdx.x, ks = blockIdx.y;
  int tx = threadIdx.x & 31;
  int ty = threadIdx.x >> 5;
  int k0 = ks*128;
  for (int idx = threadIdx.x; idx < B*32; idx += 256){
    int r = idx >> 5, c4 = idx & 31;
    float4 s = make_float4(0.f,0.f,0.f,0.f);
    #pragma unroll
    for (int p = 0; p < VSPLIT; p++){
      float4 v = ((const float4*)g_t_part[p])[r*(HID/4) + k0/4 + c4];
      s.x += v.x; s.y += v.y; s.z += v.z; s.w += v.w;
    }
    xs[r][c4*4+0]=s.x; xs[r][c4*4+1]=s.y; xs[r][c4*4+2]=s.z; xs[r][c4*4+3]=s.w;
  }
  __syncthreads();
  float4 acc[4];
  #pragma unroll
  for (int i = 0; i < 4; i++) acc[i] = make_float4(0.f,0.f,0.f,0.f);
  const float4* wp = (const float4*)Wo + (size_t)k0*(HID/4) + cb*32 + tx;
  #pragma unroll 8
  for (int k = 0; k < 128; k++){
    float4 w = wp[(size_t)k*(HID/4)];
    #pragma unroll
    for (int i = 0; i < 4; i++){
      float xv = xs[ty*4 + i][k];
      acc[i].x += xv*w.x; acc[i].y += xv*w.y; acc[i].z += xv*w.z; acc[i].w += xv*w.w;
    }
  }
  float4* op = (float4*)g_out_part[ks];
  #pragma unroll
  for (int i = 0; i < 4; i++)
    op[(size_t)(ty*4 + i)*(HID/4) + cb*32 + tx] = acc[i];
}

__global__ void k_sum(float* __restrict__ out){
  int i = blockIdx.x*blockDim.x + threadIdx.x;
  if (i < B*HID){
    float s = 0.f;
    #pragma unroll
    for (int ks = 0; ks < KSO; ks++) s += g_out_part[ks][i];
    out[i] = s;
  }
}

extern "C" void kernel_launch(void* const* d_in, const int* in_sizes, int n_in,
                              void* d_out, int out_size){
  const float* q   = (const float*)d_in[0];
  const float* kc  = (const float*)d_in[1];
  const float* kpe = (const float*)d_in[2];
  const float* kvc = (const float*)d_in[3];
  const float* Wq  = (const float*)d_in[4];
  const float* WK  = (const float*)d_in[5];
  const float* WV  = (const float*)d_in[6];
  const float* Wo  = (const float*)d_in[7];
  const int*  lens = (const int*)d_in[8];

  k_reset<<<1, 32>>>();
  k_amax<<<256, 256>>>(WK, WV);
  k_quant<<<512, 256>>>(WK, WV);
  k_qp<<<dim3(NQ/128, KSQ), 256>>>(q, Wq);
  k_qred<<<B, 256>>>(kc, kpe, lens);
  k_qk<<<dim3(KV_LORA/128, H), 256>>>();
  k_attn<<<dim3(NCHUNK, B), 256>>>(kvc, lens);
  k_comb<<<dim3(H, B), 128>>>();
  k_v<<<dim3(VSPLIT, H), 256>>>();
  k_out<<<dim3(HID/128, KSO), 256>>>(Wo);
  k_sum<<<256, 256>>>((float*)d_out);
}

// round 5
// speedup vs baseline: 1.9403x; 1.4537x over previous
#include <cuda_runtime.h>
#include <cuda_fp8.h>
#include <math.h>

#define B 32
#define S 4096
#define H 16
#define KV_LORA 512
#define NOPE 128
#define ROPE 64
#define QKD 192
#define VD 128
#define QIN 1536
#define HID 2048
#define DKV 576
#define NQ (H*QKD)
#define SCALEF 0.07216878364870323f

#define NCHUNK 16
#define CHUNK 256
#define TILE 16
#define KSQ 32
#define KSO 32
#define VS 8

typedef unsigned long long ull;

// ---------------- packed f32x2 helpers ----------------
__device__ __forceinline__ ull pk2(float x, float y){
  ull r; asm("mov.b64 %0, {%1, %2};" : "=l"(r) : "f"(x), "f"(y)); return r;
}
__device__ __forceinline__ float2 upk2(ull v){
  float2 r; asm("mov.b64 {%0, %1}, %2;" : "=f"(r.x), "=f"(r.y) : "l"(v)); return r;
}
__device__ __forceinline__ ull ffma2(ull a, ull b, ull c){
  ull d; asm("fma.rn.f32x2 %0, %1, %2, %3;" : "=l"(d) : "l"(a), "l"(b), "l"(c)); return d;
}
__device__ __forceinline__ ull fmul2(ull a, ull b){
  ull d; asm("mul.rn.f32x2 %0, %1, %2;" : "=l"(d) : "l"(a), "l"(b)); return d;
}
__device__ __forceinline__ ull fadd2(ull a, ull b){
  ull d; asm("add.rn.f32x2 %0, %1, %2;" : "=l"(d) : "l"(a), "l"(b)); return d;
}

// ---------------- device scratch ----------------
static __device__ unsigned g_amax[2];
static __device__ float g_wscale[2];                 // 1/sK, 1/sV
static __device__ unsigned char g_WK8[H*KV_LORA*NOPE];
static __device__ unsigned char g_WV8[H*VD*KV_LORA];
static __device__ float g_qp_part[KSQ][B*NQ];
static __device__ float g_qn[B*H*NOPE];
static __device__ float g_qf[B*H*DKV];               // pre-scaled by SCALEF
static __device__ float g_newkv[B*DKV];
static __device__ float g_m[B*H*NCHUNK];
static __device__ float g_l[B*H*NCHUNK];
static __device__ float g_opart[B*H*NCHUNK*KV_LORA];
static __device__ float g_o[B*H*KV_LORA];
static __device__ float g_t_part[VS][B*HID];
static __device__ float g_t[B*HID];
static __device__ float g_out_part[KSO][B*HID];

__global__ void k_reset(){
  if (threadIdx.x < 2) g_amax[threadIdx.x] = 0u;
}

__global__ void k_amax(const float* __restrict__ WK, const float* __restrict__ WV){
  const int N4 = (H*KV_LORA*NOPE)/4;
  const float4* WK4 = (const float4*)WK;
  const float4* WV4 = (const float4*)WV;
  float m0 = 0.f, m1 = 0.f;
  for (int i = blockIdx.x*blockDim.x + threadIdx.x; i < N4; i += gridDim.x*blockDim.x){
    float4 a = WK4[i], b = WV4[i];
    m0 = fmaxf(m0, fmaxf(fmaxf(fabsf(a.x),fabsf(a.y)), fmaxf(fabsf(a.z),fabsf(a.w))));
    m1 = fmaxf(m1, fmaxf(fmaxf(fabsf(b.x),fabsf(b.y)), fmaxf(fabsf(b.z),fabsf(b.w))));
  }
  #pragma unroll
  for (int off = 16; off; off >>= 1){
    m0 = fmaxf(m0, __shfl_xor_sync(0xffffffffu, m0, off));
    m1 = fmaxf(m1, __shfl_xor_sync(0xffffffffu, m1, off));
  }
  __shared__ float s0[8], s1[8];
  int w = threadIdx.x >> 5;
  if ((threadIdx.x & 31) == 0){ s0[w] = m0; s1[w] = m1; }
  __syncthreads();
  if (threadIdx.x == 0){
    #pragma unroll
    for (int i = 1; i < 8; i++){ m0 = fmaxf(m0, s0[i]); m1 = fmaxf(m1, s1[i]); }
    atomicMax(&g_amax[0], __float_as_uint(m0));
    atomicMax(&g_amax[1], __float_as_uint(m1));
  }
}

__device__ __forceinline__ unsigned q8(float v, float s){
  float x = fminf(fmaxf(v*s, -448.f), 448.f);
  return (unsigned)__nv_cvt_float_to_fp8(x, __NV_SATFINITE, __NV_E4M3);
}
__device__ __forceinline__ float fp8tf(unsigned char b){
  __half_raw h = __nv_cvt_fp8_to_halfraw((__nv_fp8_storage_t)b, __NV_E4M3);
  return __half2float(*(__half*)&h);
}

__global__ void k_quant(const float* __restrict__ WK, const float* __restrict__ WV){
  const int N16 = (H*KV_LORA*NOPE)/16;
  float aK = fmaxf(__uint_as_float(g_amax[0]), 1e-10f);
  float aV = fmaxf(__uint_as_float(g_amax[1]), 1e-10f);
  float sK = 448.f / aK, sV = 448.f / aV;
  if (blockIdx.x == 0 && threadIdx.x == 0){ g_wscale[0] = 1.f/sK; g_wscale[1] = 1.f/sV; }
  const float4* WK4 = (const float4*)WK;
  const float4* WV4 = (const float4*)WV;
  uint4* OK = (uint4*)g_WK8;
  uint4* OV = (uint4*)g_WV8;
  for (int i = blockIdx.x*blockDim.x + threadIdx.x; i < N16; i += gridDim.x*blockDim.x){
    uint4 ok, ov;
    unsigned* po = &ok.x;
    unsigned* pv = &ov.x;
    #pragma unroll
    for (int j = 0; j < 4; j++){
      float4 a = WK4[i*4 + j];
      po[j] = q8(a.x,sK) | (q8(a.y,sK)<<8) | (q8(a.z,sK)<<16) | (q8(a.w,sK)<<24);
      float4 b = WV4[i*4 + j];
      pv[j] = q8(b.x,sV) | (q8(b.y,sV)<<8) | (q8(b.z,sV)<<16) | (q8(b.w,sV)<<24);
    }
    OK[i] = ok; OV[i] = ov;
  }
}

// ---------------- qp = q @ Wq: KSQ=32 splits, 768 CTAs ----------------
__global__ void __launch_bounds__(256) k_qp(const float* __restrict__ q,
                                            const float* __restrict__ Wq){
  __shared__ float xs[B][48];
  int cb = blockIdx.x, ks = blockIdx.y;
  int tx = threadIdx.x & 31;
  int ty = threadIdx.x >> 5;
  int k0 = ks*48;
  const float4* q4 = (const float4*)q;
  for (int idx = threadIdx.x; idx < B*12; idx += 256){
    int r = idx/12, c4 = idx - r*12;
    float4 v = q4[r*(QIN/4) + k0/4 + c4];
    xs[r][c4*4+0]=v.x; xs[r][c4*4+1]=v.y; xs[r][c4*4+2]=v.z; xs[r][c4*4+3]=v.w;
  }
  __syncthreads();
  float4 acc[4];
  #pragma unroll
  for (int i = 0; i < 4; i++) acc[i] = make_float4(0.f,0.f,0.f,0.f);
  const float4* wp = (const float4*)Wq + (size_t)k0*(NQ/4) + cb*32 + tx;
  #pragma unroll 8
  for (int k = 0; k < 48; k++){
    float4 w = wp[(size_t)k*(NQ/4)];
    #pragma unroll
    for (int i = 0; i < 4; i++){
      float xv = xs[ty*4 + i][k];
      acc[i].x += xv*w.x; acc[i].y += xv*w.y; acc[i].z += xv*w.z; acc[i].w += xv*w.w;
    }
  }
  float4* op = (float4*)g_qp_part[ks];
  #pragma unroll
  for (int i = 0; i < 4; i++)
    op[(size_t)(ty*4 + i)*(NQ/4) + cb*32 + tx] = acc[i];
}

// ---------------- reduce qp partials + rope + new_kv (192 CTAs) ----------------
__global__ void __launch_bounds__(256) k_qred(const float* __restrict__ kc,
                                              const float* __restrict__ kpe,
                                              const int* __restrict__ kv_lens){
  int b = blockIdx.x, cy = blockIdx.y;
  int tid = threadIdx.x;
  __shared__ float qs[512];
  int cbase = cy*512;
  #pragma unroll
  for (int j = 0; j < 2; j++){
    int col = tid + j*256;
    float s = 0.f;
    #pragma unroll
    for (int ks = 0; ks < KSQ; ks++) s += g_qp_part[ks][b*NQ + cbase + col];
    qs[col] = s;
  }
  __syncthreads();
  int pos = kv_lens[b];
  #pragma unroll
  for (int j = 0; j < 2; j++){
    int col = tid + j*256;
    int gc = cbase + col;
    int h = gc/192, off = gc - h*192;
    if (off < 128){
      g_qn[(b*H + h)*NOPE + off] = qs[col];
    } else if (off < 160){
      int i = off - 128;
      double inv = exp(-((2.0*i)/64.0) * 9.210340371976184);
      double ang = (double)pos * inv;
      float cs = (float)cos(ang), sn = (float)sin(ang);
      float x1 = qs[col], x2 = qs[col+32];
      float* qf = g_qf + (size_t)(b*H + h)*DKV;
      qf[KV_LORA + i]      = (x1*cs - x2*sn)*SCALEF;
      qf[KV_LORA + 32 + i] = (x2*cs + x1*sn)*SCALEF;
    }
  }
  if (cy == 0){
    for (int j = tid; j < KV_LORA; j += 256) g_newkv[b*DKV + j] = kc[b*KV_LORA + j];
    if (tid < 32){
      int i = tid;
      double inv = exp(-((2.0*i)/64.0)*9.210340371976184);
      double ang = (double)pos*inv;
      float cs = (float)cos(ang), sn = (float)sin(ang);
      float k1 = kpe[b*ROPE + i], k2 = kpe[b*ROPE + 32 + i];
      g_newkv[b*DKV + KV_LORA + i]      = k1*cs - k2*sn;
      g_newkv[b*DKV + KV_LORA + 32 + i] = k2*cs + k1*sn;
    }
  }
}

// ---------------- ql_nope = q_nope @ W_Kd^T (fp8 weights, 128 CTAs) ----------------
__global__ void __launch_bounds__(256) k_qk(){
  int h = blockIdx.y, c0 = blockIdx.x*64;
  int tid = threadIdx.x;
  int cc = tid & 63, rg = tid >> 6;
  __shared__ float qn_s[B][NOPE];
  __shared__ float ws[64][33];
  float invK = g_wscale[0];
  for (int idx = tid; idx < B*(NOPE/4); idx += 256){
    int r = idx >> 5, d4 = idx & 31;
    float4 v = ((const float4*)(g_qn + (size_t)(r*H + h)*NOPE))[d4];
    qn_s[r][d4*4+0]=v.x; qn_s[r][d4*4+1]=v.y; qn_s[r][d4*4+2]=v.z; qn_s[r][d4*4+3]=v.w;
  }
  float acc[8];
  #pragma unroll
  for (int i = 0; i < 8; i++) acc[i] = 0.f;
  for (int db = 0; db < NOPE; db += 32){
    __syncthreads();
    #pragma unroll
    for (int it = 0; it < 2; it++){
      int idx = tid + it*256;
      int c = idx >> 3, d4 = (idx & 7)*4;
      const unsigned char* p = g_WK8 + (size_t)(h*KV_LORA + c0 + c)*NOPE + db + d4;
      uchar4 v = *(const uchar4*)p;
      ws[c][d4+0]=fp8tf(v.x); ws[c][d4+1]=fp8tf(v.y); ws[c][d4+2]=fp8tf(v.z); ws[c][d4+3]=fp8tf(v.w);
    }
    __syncthreads();
    #pragma unroll
    for (int d = 0; d < 32; d++){
      float w = ws[cc][d];
      #pragma unroll
      for (int r = 0; r < 8; r++)
        acc[r] += qn_s[rg*8 + r][db + d]*w;
    }
  }
  float sc = SCALEF*invK;
  #pragma unroll
  for (int r = 0; r < 8; r++){
    int b = rg*8 + r;
    g_qf[(size_t)(b*H + h)*DKV + c0 + cc] = acc[r]*sc;
  }
}

// ---------------- flash attention: cp.async double-buffer + fold reduce ----------------
__global__ void __launch_bounds__(256) k_attn(const float* __restrict__ kv_cache,
                                              const int* __restrict__ kv_lens){
  extern __shared__ float kvs[];   // [2][TILE][DKV]
  int chunk = blockIdx.x, b = blockIdx.y;
  int len = kv_lens[b];
  int s_begin = chunk*CHUNK;
  if (s_begin > len) return;
  int s_end = min(s_begin + CHUNK, len + 1);
  int T = (s_end - s_begin + TILE - 1)/TILE;

  int tid = threadIdx.x;
  int warp = tid >> 5, lane = tid & 31;
  int wg = warp & 3, rh = warp >> 2, hg = wg*4;
  int myh = lane >> 3, myr = lane & 7;
  int r0 = rh*8;

  __shared__ float mlx[4][4][2];

  ull q2[4][9];
  #pragma unroll
  for (int h = 0; h < 4; h++){
    const ull* qf = (const ull*)(g_qf + (size_t)(b*H + hg + h)*DKV);
    #pragma unroll
    for (int j = 0; j < 9; j++) q2[h][j] = qf[j*32 + lane];
  }

  ull acc[4][8];
  #pragma unroll
  for (int h = 0; h < 4; h++)
    #pragma unroll
    for (int j = 0; j < 8; j++) acc[h][j] = 0ull;
  float mh = -1e30f, lh = 0.f;   // per-lane state for head hg+myh

  // tile loader (cp.async)
  auto load_tile = [&](int t, int buf){
    int t0 = s_begin + t*TILE;
    int rows = min(TILE, s_end - t0);
    float* dst = kvs + buf*(TILE*DKV);
    for (int idx = tid; idx < rows*144; idx += 256){
      int r = idx/144, c4 = idx - r*144;
      int s = t0 + r;
      const float* src = (s == len) ? (g_newkv + b*DKV + c4*4)
                                    : (kv_cache + ((size_t)b*S + s)*DKV + c4*4);
      unsigned sa = (unsigned)__cvta_generic_to_shared(dst + r*DKV + c4*4);
      asm volatile("cp.async.cg.shared.global [%0], [%1], 16;" :: "r"(sa), "l"(src));
    }
    for (int idx = tid + rows*144; idx < TILE*144; idx += 256){
      int r = idx/144, c4 = idx - r*144;
      *(float4*)(dst + r*DKV + c4*4) = make_float4(0.f,0.f,0.f,0.f);
    }
    asm volatile("cp.async.commit_group;" ::: "memory");
  };

  load_tile(0, 0);
  for (int t = 0; t < T; t++){
    if (t + 1 < T){
      load_tile(t+1, (t+1)&1);
      asm volatile("cp.async.wait_group 1;" ::: "memory");
    } else {
      asm volatile("cp.async.wait_group 0;" ::: "memory");
    }
    __syncthreads();
    const float* kb = kvs + (t&1)*(TILE*DKV);
    int t0 = s_begin + t*TILE;

    // ---- scores: partials for 32 values (4 heads x 8 rows) ----
    float x[32];
    #pragma unroll
    for (int r = 0; r < 8; r++){
      const ull* row = (const ull*)(kb + (r0 + r)*DKV);
      ull sa0=0, sa1=0, sa2=0, sa3=0;
      #pragma unroll
      for (int j = 0; j < 9; j++){
        ull kv = row[j*32 + lane];
        sa0 = ffma2(q2[0][j], kv, sa0);
        sa1 = ffma2(q2[1][j], kv, sa1);
        sa2 = ffma2(q2[2][j], kv, sa2);
        sa3 = ffma2(q2[3][j], kv, sa3);
      }
      float2 v0=upk2(sa0), v1=upk2(sa1), v2=upk2(sa2), v3=upk2(sa3);
      x[0*8+r] = v0.x+v0.y; x[1*8+r] = v1.x+v1.y;
      x[2*8+r] = v2.x+v2.y; x[3*8+r] = v3.x+v3.y;
    }
    // fold: lane L ends with total of value L (h = L>>3, r = L&7)
    #pragma unroll
    for (int off = 16; off >= 1; off >>= 1){
      bool hi = (lane & off) != 0;
      #pragma unroll
      for (int i = 0; i < off; i++){
        float send = hi ? x[i] : x[i+off];
        float recv = __shfl_xor_sync(0xffffffffu, send, off);
        x[i] = (hi ? x[i+off] : x[i]) + recv;
      }
    }
    bool valid = (t0 + r0 + myr) < s_end;
    float s = valid ? x[0] : -1e30f;

    // per-head softmax within 8-lane group
    float tm = s;
    tm = fmaxf(tm, __shfl_xor_sync(0xffffffffu, tm, 4));
    tm = fmaxf(tm, __shfl_xor_sync(0xffffffffu, tm, 2));
    tm = fmaxf(tm, __shfl_xor_sync(0xffffffffu, tm, 1));
    float nm = fmaxf(mh, tm);
    float cf = __expf(mh - nm);
    mh = nm;
    float p = valid ? __expf(s - nm) : 0.f;
    float sp = p;
    sp += __shfl_xor_sync(0xffffffffu, sp, 4);
    sp += __shfl_xor_sync(0xffffffffu, sp, 2);
    sp += __shfl_xor_sync(0xffffffffu, sp, 1);
    lh = lh*cf + sp;

    #pragma unroll
    for (int h = 0; h < 4; h++){
      float cfh = __shfl_sync(0xffffffffu, cf, h*8);
      ull c2 = pk2(cfh, cfh);
      #pragma unroll
      for (int j = 0; j < 8; j++) acc[h][j] = fmul2(acc[h][j], c2);
    }

    #pragma unroll
    for (int r = 0; r < 8; r++){
      float p0 = __shfl_sync(0xffffffffu, p, 0*8 + r);
      float p1 = __shfl_sync(0xffffffffu, p, 1*8 + r);
      float p2 = __shfl_sync(0xffffffffu, p, 2*8 + r);
      float p3 = __shfl_sync(0xffffffffu, p, 3*8 + r);
      ull pp0 = pk2(p0,p0), pp1 = pk2(p1,p1), pp2 = pk2(p2,p2), pp3 = pk2(p3,p3);
      const ull* row = (const ull*)(kb + (r0 + r)*DKV);
      #pragma unroll
      for (int j = 0; j < 8; j++){
        ull kv = row[j*32 + lane];
        acc[0][j] = ffma2(pp0, kv, acc[0][j]);
        acc[1][j] = ffma2(pp1, kv, acc[1][j]);
        acc[2][j] = ffma2(pp2, kv, acc[2][j]);
        acc[3][j] = ffma2(pp3, kv, acc[3][j]);
      }
    }
    __syncthreads();
  }

  // ---- merge row-half warps and store partials ----
  ull* bufu = (ull*)kvs;
  if (rh == 1){
    #pragma unroll
    for (int h = 0; h < 4; h++)
      #pragma unroll
      for (int j = 0; j < 8; j++)
        bufu[(size_t)(hg + h)*256 + j*32 + lane] = acc[h][j];
    if (myr == 0){ mlx[wg][myh][0] = mh; mlx[wg][myh][1] = lh; }
  }
  __syncthreads();
  if (rh == 0){
    #pragma unroll
    for (int h = 0; h < 4; h++){
      float ma = __shfl_sync(0xffffffffu, mh, h*8);
      float la = __shfl_sync(0xffffffffu, lh, h*8);
      float mb = mlx[wg][h][0], lb = mlx[wg][h][1];
      float nm = fmaxf(ma, mb);
      float ca = __expf(ma - nm), cb = __expf(mb - nm);
      float lm = la*ca + lb*cb;
      int basep = (b*H + hg + h)*NCHUNK + chunk;
      if (lane == 0){ g_m[basep] = nm; g_l[basep] = lm; }
      ull ca2 = pk2(ca,ca), cb2 = pk2(cb,cb);
      ull* op = (ull*)g_opart + (size_t)basep*256;
      #pragma unroll
      for (int j = 0; j < 8; j++)
        op[j*32 + lane] = fadd2(fmul2(acc[h][j], ca2),
                                fmul2(bufu[(size_t)(hg + h)*256 + j*32 + lane], cb2));
    }
  }
}

// ---------------- combine split-softmax partials (active chunks only) ----------------
__global__ void __launch_bounds__(128) k_comb(const int* __restrict__ kv_lens){
  int h = blockIdx.x, b = blockIdx.y;
  int tid = threadIdx.x;
  int len = kv_lens[b];
  int cmax = min(NCHUNK - 1, len >> 8);
  int base = (b*H + h)*NCHUNK;
  float mstar = -1e30f;
  for (int c = 0; c <= cmax; c++) mstar = fmaxf(mstar, g_m[base + c]);
  float lstar = 0.f;
  for (int c = 0; c <= cmax; c++) lstar += expf(g_m[base + c] - mstar) * g_l[base + c];
  float inv_l = 1.f / lstar;
  #pragma unroll
  for (int j = 0; j < KV_LORA/128; j++){
    int d = tid + j*128;
    float s = 0.f;
    for (int c = 0; c <= cmax; c++)
      s += expf(g_m[base + c] - mstar) * g_opart[(size_t)(base + c)*KV_LORA + d];
    g_o[(size_t)(b*H + h)*KV_LORA + d] = s * inv_l;
  }
}

// ---------------- t = o @ W_Vd^T (fp8 weights, 128 CTAs) ----------------
__global__ void __launch_bounds__(256) k_v(){
  int cs = blockIdx.x, h = blockIdx.y;
  int tid = threadIdx.x;
  int vv = tid & 127, rg = tid >> 7;
  __shared__ float ws[128][33];
  __shared__ float os[B][32];
  float invV = g_wscale[1];
  float acc[16];
  #pragma unroll
  for (int i = 0; i < 16; i++) acc[i] = 0.f;
  for (int cbk = 0; cbk < 64; cbk += 32){
    int c0 = cs*64 + cbk;
    __syncthreads();
    #pragma unroll
    for (int it = 0; it < 4; it++){
      int idx = tid + it*256;
      int v = idx >> 3, d4 = (idx & 7)*4;
      const unsigned char* p = g_WV8 + (size_t)(h*VD + v)*KV_LORA + c0 + d4;
      uchar4 u = *(const uchar4*)p;
      ws[v][d4+0]=fp8tf(u.x); ws[v][d4+1]=fp8tf(u.y); ws[v][d4+2]=fp8tf(u.z); ws[v][d4+3]=fp8tf(u.w);
    }
    for (int idx = tid; idx < B*8; idx += 256){
      int r = idx >> 3, d4 = (idx & 7)*4;
      float4 v = *(const float4*)(g_o + (size_t)(r*H + h)*KV_LORA + c0 + d4);
      os[r][d4+0]=v.x; os[r][d4+1]=v.y; os[r][d4+2]=v.z; os[r][d4+3]=v.w;
    }
    __syncthreads();
    #pragma unroll
    for (int d = 0; d < 32; d++){
      float w = ws[vv][d];
      #pragma unroll
      for (int r = 0; r < 16; r++)
        acc[r] += os[rg*16 + r][d]*w;
    }
  }
  #pragma unroll
  for (int r = 0; r < 16; r++){
    int b = rg*16 + r;
    g_t_part[cs][b*HID + h*VD + vv] = acc[r]*invV;
  }
}

__global__ void k_tred(){
  int i = blockIdx.x*blockDim.x + threadIdx.x;
  if (i < B*HID){
    float s = 0.f;
    #pragma unroll
    for (int p = 0; p < VS; p++) s += g_t_part[p][i];
    g_t[i] = s;
  }
}

// ---------------- out = t @ Wo (KSO=32, 512 CTAs) ----------------
__global__ void __launch_bounds__(256) k_out(const float* __restrict__ Wo){
  __shared__ float xs[B][64];
  int cb = blockIdx.x, ks = blockIdx.y;
  int tx = threadIdx.x & 31;
  int ty = threadIdx.x >> 5;
  int k0 = ks*64;
  for (int idx = threadIdx.x; idx < B*16; idx += 256){
    int r = idx >> 4, c4 = idx & 15;
    float4 v = ((const float4*)g_t)[r*(HID/4) + k0/4 + c4];
    xs[r][c4*4+0]=v.x; xs[r][c4*4+1]=v.y; xs[r][c4*4+2]=v.z; xs[r][c4*4+3]=v.w;
  }
  __syncthreads();
  float4 acc[4];
  #pragma unroll
  for (int i = 0; i < 4; i++) acc[i] = make_float4(0.f,0.f,0.f,0.f);
  const float4* wp = (const float4*)Wo + (size_t)k0*(HID/4) + cb*32 + tx;
  #pragma unroll 8
  for (int k = 0; k < 64; k++){
    float4 w = wp[(size_t)k*(HID/4)];
    #pragma unroll
    for (int i = 0; i < 4; i++){
      float xv = xs[ty*4 + i][k];
      acc[i].x += xv*w.x; acc[i].y += xv*w.y; acc[i].z += xv*w.z; acc[i].w += xv*w.w;
    }
  }
  float4* op = (float4*)g_out_part[ks];
  #pragma unroll
  for (int i = 0; i < 4; i++)
    op[(size_t)(ty*4 + i)*(HID/4) + cb*32 + tx] = acc[i];
}

__global__ void k_sum(float* __restrict__ out){
  int i = blockIdx.x*blockDim.x + threadIdx.x;
  if (i < B*HID){
    float s = 0.f;
    #pragma unroll
    for (int ks = 0; ks < KSO; ks++) s += g_out_part[ks][i];
    out[i] = s;
  }
}

extern "C" void kernel_launch(void* const* d_in, const int* in_sizes, int n_in,
                              void* d_out, int out_size){
  const float* q   = (const float*)d_in[0];
  const float* kc  = (const float*)d_in[1];
  const float* kpe = (const float*)d_in[2];
  const float* kvc = (const float*)d_in[3];
  const float* Wq  = (const float*)d_in[4];
  const float* WK  = (const float*)d_in[5];
  const float* WV  = (const float*)d_in[6];
  const float* Wo  = (const float*)d_in[7];
  const int*  lens = (const int*)d_in[8];

  cudaFuncSetAttribute(k_attn, cudaFuncAttributeMaxDynamicSharedMemorySize, 2*TILE*DKV*4);

  k_reset<<<1, 32>>>();
  k_amax<<<256, 256>>>(WK, WV);
  k_quant<<<512, 256>>>(WK, WV);
  k_qp<<<dim3(NQ/128, KSQ), 256>>>(q, Wq);
  k_qred<<<dim3(B, NQ/512), 256>>>(kc, kpe, lens);
  k_qk<<<dim3(KV_LORA/64, H), 256>>>();
  k_attn<<<dim3(NCHUNK, B), 256, 2*TILE*DKV*4>>>(kvc, lens);
  k_comb<<<dim3(H, B), 128>>>(lens);
  k_v<<<dim3(VS, H), 256>>>();
  k_tred<<<256, 256>>>();
  k_out<<<dim3(HID/128, KSO), 256>>>(Wo);
  k_sum<<<256, 256>>>((float*)d_out);
}

// round 6
// speedup vs baseline: 2.2057x; 1.1367x over previous
#include <cuda_runtime.h>
#include <cuda_fp8.h>
#include <math.h>

#define B 32
#define S 4096
#define H 16
#define KV_LORA 512
#define NOPE 128
#define ROPE 64
#define QKD 192
#define VD 128
#define QIN 1536
#define HID 2048
#define DKV 576
#define NQ (H*QKD)
#define SCALEF 0.07216878364870323f

#define NCHUNK 16
#define CHUNK 256
#define TILE 16
#define KSQ 32
#define KSO 32
#define VS 8

typedef unsigned long long ull;

// ---------------- packed f32x2 helpers ----------------
__device__ __forceinline__ ull pk2(float x, float y){
  ull r; asm("mov.b64 %0, {%1, %2};" : "=l"(r) : "f"(x), "f"(y)); return r;
}
__device__ __forceinline__ float2 upk2(ull v){
  float2 r; asm("mov.b64 {%0, %1}, %2;" : "=f"(r.x), "=f"(r.y) : "l"(v)); return r;
}
__device__ __forceinline__ ull ffma2(ull a, ull b, ull c){
  ull d; asm("fma.rn.f32x2 %0, %1, %2, %3;" : "=l"(d) : "l"(a), "l"(b), "l"(c)); return d;
}
__device__ __forceinline__ ull fmul2(ull a, ull b){
  ull d; asm("mul.rn.f32x2 %0, %1, %2;" : "=l"(d) : "l"(a), "l"(b)); return d;
}
__device__ __forceinline__ ull fadd2(ull a, ull b){
  ull d; asm("add.rn.f32x2 %0, %1, %2;" : "=l"(d) : "l"(a), "l"(b)); return d;
}

// ---------------- device scratch ----------------
static __device__ unsigned g_amax[2];                // zero-init; atomicMax idempotent across replays
static __device__ float g_wscale[2];
static __device__ unsigned char g_WK8[H*KV_LORA*NOPE];
static __device__ unsigned char g_WV8[H*VD*KV_LORA];
static __device__ float g_qp_part[KSQ][B*NQ];
static __device__ float g_qn[B*H*NOPE];
static __device__ float g_qf[B*H*DKV];               // pre-scaled by SCALEF
static __device__ float g_newkv[B*DKV];
static __device__ float g_m[B*H*NCHUNK];
static __device__ float g_l[B*H*NCHUNK];
static __device__ float g_opart[B*H*NCHUNK*KV_LORA];
static __device__ float g_o[B*H*KV_LORA];
static __device__ float g_t_part[VS][B*HID];
static __device__ float g_t[B*HID];
static __device__ float g_out_part[KSO][B*HID];

__global__ void k_amax(const float* __restrict__ WK, const float* __restrict__ WV){
  const int N4 = (H*KV_LORA*NOPE)/4;
  const float4* WK4 = (const float4*)WK;
  const float4* WV4 = (const float4*)WV;
  float m0 = 0.f, m1 = 0.f;
  for (int i = blockIdx.x*blockDim.x + threadIdx.x; i < N4; i += gridDim.x*blockDim.x){
    float4 a = WK4[i], b = WV4[i];
    m0 = fmaxf(m0, fmaxf(fmaxf(fabsf(a.x),fabsf(a.y)), fmaxf(fabsf(a.z),fabsf(a.w))));
    m1 = fmaxf(m1, fmaxf(fmaxf(fabsf(b.x),fabsf(b.y)), fmaxf(fabsf(b.z),fabsf(b.w))));
  }
  #pragma unroll
  for (int off = 16; off; off >>= 1){
    m0 = fmaxf(m0, __shfl_xor_sync(0xffffffffu, m0, off));
    m1 = fmaxf(m1, __shfl_xor_sync(0xffffffffu, m1, off));
  }
  __shared__ float s0[8], s1[8];
  int w = threadIdx.x >> 5;
  if ((threadIdx.x & 31) == 0){ s0[w] = m0; s1[w] = m1; }
  __syncthreads();
  if (threadIdx.x == 0){
    #pragma unroll
    for (int i = 1; i < 8; i++){ m0 = fmaxf(m0, s0[i]); m1 = fmaxf(m1, s1[i]); }
    atomicMax(&g_amax[0], __float_as_uint(m0));
    atomicMax(&g_amax[1], __float_as_uint(m1));
  }
}

__device__ __forceinline__ unsigned q8(float v, float s){
  float x = fminf(fmaxf(v*s, -448.f), 448.f);
  return (unsigned)__nv_cvt_float_to_fp8(x, __NV_SATFINITE, __NV_E4M3);
}
__device__ __forceinline__ float fp8tf(unsigned char b){
  __half_raw h = __nv_cvt_fp8_to_halfraw((__nv_fp8_storage_t)b, __NV_E4M3);
  return __half2float(*(__half*)&h);
}

__global__ void k_quant(const float* __restrict__ WK, const float* __restrict__ WV){
  const int N16 = (H*KV_LORA*NOPE)/16;
  float aK = fmaxf(__uint_as_float(g_amax[0]), 1e-10f);
  float aV = fmaxf(__uint_as_float(g_amax[1]), 1e-10f);
  float sK = 448.f / aK, sV = 448.f / aV;
  if (blockIdx.x == 0 && threadIdx.x == 0){ g_wscale[0] = 1.f/sK; g_wscale[1] = 1.f/sV; }
  const float4* WK4 = (const float4*)WK;
  const float4* WV4 = (const float4*)WV;
  uint4* OK = (uint4*)g_WK8;
  uint4* OV = (uint4*)g_WV8;
  for (int i = blockIdx.x*blockDim.x + threadIdx.x; i < N16; i += gridDim.x*blockDim.x){
    uint4 ok, ov;
    unsigned* po = &ok.x;
    unsigned* pv = &ov.x;
    #pragma unroll
    for (int j = 0; j < 4; j++){
      float4 a = WK4[i*4 + j];
      po[j] = q8(a.x,sK) | (q8(a.y,sK)<<8) | (q8(a.z,sK)<<16) | (q8(a.w,sK)<<24);
      float4 b = WV4[i*4 + j];
      pv[j] = q8(b.x,sV) | (q8(b.y,sV)<<8) | (q8(b.z,sV)<<16) | (q8(b.w,sV)<<24);
    }
    OK[i] = ok; OV[i] = ov;
  }
}

// ---------------- qp = q @ Wq : cp.async staged weights + f32x2 FMA ----------------
__global__ void __launch_bounds__(256) k_qp(const float* __restrict__ q,
                                            const float* __restrict__ Wq){
  __shared__ float xs[B][48];
  __shared__ __align__(16) float ws[48][128];
  int cb = blockIdx.x, ks = blockIdx.y;
  int tid = threadIdx.x;
  int tx = tid & 31, ty = tid >> 5;
  int k0 = ks*48;
  {
    int row = tid >> 5;
    int col = (tid & 31)*4;
    #pragma unroll
    for (int s = 0; s < 6; s++){
      int r = s*8 + row;
      const float* src = Wq + (size_t)(k0 + r)*NQ + cb*128 + col;
      unsigned sa = (unsigned)__cvta_generic_to_shared(&ws[r][col]);
      asm volatile("cp.async.cg.shared.global [%0], [%1], 16;" :: "r"(sa), "l"(src));
    }
    asm volatile("cp.async.commit_group;" ::: "memory");
  }
  const float4* q4 = (const float4*)q;
  #pragma unroll
  for (int it = 0; it < 2; it++){
    int idx = tid + it*256;
    if (idx < B*12){
      int r = idx/12, c4 = idx - r*12;
      float4 v = q4[r*(QIN/4) + (k0>>2) + c4];
      xs[r][c4*4+0]=v.x; xs[r][c4*4+1]=v.y; xs[r][c4*4+2]=v.z; xs[r][c4*4+3]=v.w;
    }
  }
  asm volatile("cp.async.wait_group 0;" ::: "memory");
  __syncthreads();
  ull acc[8] = {};
  #pragma unroll 8
  for (int k = 0; k < 48; k++){
    ulonglong2 w2 = ((const ulonglong2*)ws[k])[tx];
    #pragma unroll
    for (int i = 0; i < 4; i++){
      float xv = xs[ty*4+i][k];
      ull xv2 = pk2(xv, xv);
      acc[i*2]   = ffma2(xv2, w2.x, acc[i*2]);
      acc[i*2+1] = ffma2(xv2, w2.y, acc[i*2+1]);
    }
  }
  float4* op = (float4*)g_qp_part[ks];
  #pragma unroll
  for (int i = 0; i < 4; i++){
    float2 a = upk2(acc[i*2]), b = upk2(acc[i*2+1]);
    op[(size_t)(ty*4+i)*(NQ/4) + cb*32 + tx] = make_float4(a.x,a.y,b.x,b.y);
  }
}

// ---------------- reduce qp partials + rope + new_kv ----------------
__global__ void __launch_bounds__(256) k_qred(const float* __restrict__ kc,
                                              const float* __restrict__ kpe,
                                              const int* __restrict__ kv_lens){
  int b = blockIdx.x, cy = blockIdx.y;
  int tid = threadIdx.x;
  __shared__ float qs[512];
  int cbase = cy*512;
  #pragma unroll
  for (int j = 0; j < 2; j++){
    int col = tid + j*256;
    float s = 0.f;
    #pragma unroll
    for (int ks = 0; ks < KSQ; ks++) s += g_qp_part[ks][b*NQ + cbase + col];
    qs[col] = s;
  }
  __syncthreads();
  int pos = kv_lens[b];
  #pragma unroll
  for (int j = 0; j < 2; j++){
    int col = tid + j*256;
    int gc = cbase + col;
    int h = gc/192, off = gc - h*192;
    if (off < 128){
      g_qn[(b*H + h)*NOPE + off] = qs[col];
    } else if (off < 160){
      int i = off - 128;
      double inv = exp(-((2.0*i)/64.0) * 9.210340371976184);
      double ang = (double)pos * inv;
      float cs = (float)cos(ang), sn = (float)sin(ang);
      float x1 = qs[col], x2 = qs[col+32];
      float* qf = g_qf + (size_t)(b*H + h)*DKV;
      qf[KV_LORA + i]      = (x1*cs - x2*sn)*SCALEF;
      qf[KV_LORA + 32 + i] = (x2*cs + x1*sn)*SCALEF;
    }
  }
  if (cy == 0){
    for (int j = tid; j < KV_LORA; j += 256) g_newkv[b*DKV + j] = kc[b*KV_LORA + j];
    if (tid < 32){
      int i = tid;
      double inv = exp(-((2.0*i)/64.0)*9.210340371976184);
      double ang = (double)pos*inv;
      float cs = (float)cos(ang), sn = (float)sin(ang);
      float k1 = kpe[b*ROPE + i], k2 = kpe[b*ROPE + 32 + i];
      g_newkv[b*DKV + KV_LORA + i]      = k1*cs - k2*sn;
      g_newkv[b*DKV + KV_LORA + 32 + i] = k2*cs + k1*sn;
    }
  }
}

// ---------------- ql_nope = q_nope @ W_Kd^T (fp8 weights) ----------------
__global__ void __launch_bounds__(256) k_qk(){
  int h = blockIdx.y, c0 = blockIdx.x*64;
  int tid = threadIdx.x;
  int cc = tid & 63, rg = tid >> 6;
  __shared__ float qn_s[B][NOPE];
  __shared__ float ws[64][33];
  float invK = g_wscale[0];
  for (int idx = tid; idx < B*(NOPE/4); idx += 256){
    int r = idx >> 5, d4 = idx & 31;
    float4 v = ((const float4*)(g_qn + (size_t)(r*H + h)*NOPE))[d4];
    qn_s[r][d4*4+0]=v.x; qn_s[r][d4*4+1]=v.y; qn_s[r][d4*4+2]=v.z; qn_s[r][d4*4+3]=v.w;
  }
  float acc[8];
  #pragma unroll
  for (int i = 0; i < 8; i++) acc[i] = 0.f;
  for (int db = 0; db < NOPE; db += 32){
    __syncthreads();
    #pragma unroll
    for (int it = 0; it < 2; it++){
      int idx = tid + it*256;
      int c = idx >> 3, d4 = (idx & 7)*4;
      const unsigned char* p = g_WK8 + (size_t)(h*KV_LORA + c0 + c)*NOPE + db + d4;
      uchar4 v = *(const uchar4*)p;
      ws[c][d4+0]=fp8tf(v.x); ws[c][d4+1]=fp8tf(v.y); ws[c][d4+2]=fp8tf(v.z); ws[c][d4+3]=fp8tf(v.w);
    }
    __syncthreads();
    #pragma unroll
    for (int d = 0; d < 32; d++){
      float w = ws[cc][d];
      #pragma unroll
      for (int r = 0; r < 8; r++)
        acc[r] += qn_s[rg*8 + r][db + d]*w;
    }
  }
  float sc = SCALEF*invK;
  #pragma unroll
  for (int r = 0; r < 8; r++){
    int b = rg*8 + r;
    g_qf[(size_t)(b*H + h)*DKV + c0 + cc] = acc[r]*sc;
  }
}

// ---------------- flash attention: 3-deep cp.async pipeline, 1 barrier/tile ----------------
__global__ void __launch_bounds__(256) k_attn(const float* __restrict__ kv_cache,
                                              const int* __restrict__ kv_lens){
  extern __shared__ float kvs[];   // [3][TILE][DKV]
  int chunk = blockIdx.x, b = blockIdx.y;
  int len = kv_lens[b];
  int s_begin = chunk*CHUNK;
  if (s_begin > len) return;
  int s_end = min(s_begin + CHUNK, len + 1);
  int T = (s_end - s_begin + TILE - 1)/TILE;

  int tid = threadIdx.x;
  int warp = tid >> 5, lane = tid & 31;
  int wg = warp & 3, rh = warp >> 2, hg = wg*4;
  int myh = lane >> 3, myr = lane & 7;
  int r0 = rh*8;

  __shared__ float mlx[4][4][2];

  ull q2[4][9];
  #pragma unroll
  for (int h = 0; h < 4; h++){
    const ull* qf = (const ull*)(g_qf + (size_t)(b*H + hg + h)*DKV);
    #pragma unroll
    for (int j = 0; j < 9; j++) q2[h][j] = qf[j*32 + lane];
  }

  ull acc[4][8];
  #pragma unroll
  for (int h = 0; h < 4; h++)
    #pragma unroll
    for (int j = 0; j < 8; j++) acc[h][j] = 0ull;
  float mh = -1e30f, lh = 0.f;

  auto load_tile = [&](int t, int buf){
    int t0 = s_begin + t*TILE;
    int rows = min(TILE, s_end - t0);
    float* dst = kvs + buf*(TILE*DKV);
    for (int idx = tid; idx < rows*144; idx += 256){
      int r = idx/144, c4 = idx - r*144;
      int s = t0 + r;
      const float* src = (s == len) ? (g_newkv + b*DKV + c4*4)
                                    : (kv_cache + ((size_t)b*S + s)*DKV + c4*4);
      unsigned sa = (unsigned)__cvta_generic_to_shared(dst + r*DKV + c4*4);
      asm volatile("cp.async.cg.shared.global [%0], [%1], 16;" :: "r"(sa), "l"(src));
    }
    for (int idx = tid + rows*144; idx < TILE*144; idx += 256){
      int r = idx/144, c4 = idx - r*144;
      *(float4*)(dst + r*DKV + c4*4) = make_float4(0.f,0.f,0.f,0.f);
    }
    asm volatile("cp.async.commit_group;" ::: "memory");
  };

  load_tile(0, 0);
  if (T > 1) load_tile(1, 1);
  for (int t = 0; t < T; t++){
    if (t < T-1) asm volatile("cp.async.wait_group 1;" ::: "memory");
    else         asm volatile("cp.async.wait_group 0;" ::: "memory");
    __syncthreads();
    if (t + 2 < T) load_tile(t+2, (t+2)%3);

    const float* kb = kvs + (t%3)*(TILE*DKV);
    int t0 = s_begin + t*TILE;

    // ---- scores ----
    float x[32];
    #pragma unroll
    for (int r = 0; r < 8; r++){
      const ull* row = (const ull*)(kb + (r0 + r)*DKV);
      ull sa0=0, sa1=0, sa2=0, sa3=0;
      #pragma unroll
      for (int j = 0; j < 9; j++){
        ull kv = row[j*32 + lane];
        sa0 = ffma2(q2[0][j], kv, sa0);
        sa1 = ffma2(q2[1][j], kv, sa1);
        sa2 = ffma2(q2[2][j], kv, sa2);
        sa3 = ffma2(q2[3][j], kv, sa3);
      }
      float2 v0=upk2(sa0), v1=upk2(sa1), v2=upk2(sa2), v3=upk2(sa3);
      x[0*8+r] = v0.x+v0.y; x[1*8+r] = v1.x+v1.y;
      x[2*8+r] = v2.x+v2.y; x[3*8+r] = v3.x+v3.y;
    }
    #pragma unroll
    for (int off = 16; off >= 1; off >>= 1){
      bool hi = (lane & off) != 0;
      #pragma unroll
      for (int i = 0; i < off; i++){
        float send = hi ? x[i] : x[i+off];
        float recv = __shfl_xor_sync(0xffffffffu, send, off);
        x[i] = (hi ? x[i+off] : x[i]) + recv;
      }
    }
    bool valid = (t0 + r0 + myr) < s_end;
    float s = valid ? x[0] : -1e30f;

    float tm = s;
    tm = fmaxf(tm, __shfl_xor_sync(0xffffffffu, tm, 4));
    tm = fmaxf(tm, __shfl_xor_sync(0xffffffffu, tm, 2));
    tm = fmaxf(tm, __shfl_xor_sync(0xffffffffu, tm, 1));
    float nm = fmaxf(mh, tm);
    float cf = __expf(mh - nm);
    mh = nm;
    float p = valid ? __expf(s - nm) : 0.f;
    float sp = p;
    sp += __shfl_xor_sync(0xffffffffu, sp, 4);
    sp += __shfl_xor_sync(0xffffffffu, sp, 2);
    sp += __shfl_xor_sync(0xffffffffu, sp, 1);
    lh = lh*cf + sp;

    #pragma unroll
    for (int h = 0; h < 4; h++){
      float cfh = __shfl_sync(0xffffffffu, cf, h*8);
      ull c2 = pk2(cfh, cfh);
      #pragma unroll
      for (int j = 0; j < 8; j++) acc[h][j] = fmul2(acc[h][j], c2);
    }

    #pragma unroll
    for (int r = 0; r < 8; r++){
      float p0 = __shfl_sync(0xffffffffu, p, 0*8 + r);
      float p1 = __shfl_sync(0xffffffffu, p, 1*8 + r);
      float p2 = __shfl_sync(0xffffffffu, p, 2*8 + r);
      float p3 = __shfl_sync(0xffffffffu, p, 3*8 + r);
      ull pp0 = pk2(p0,p0), pp1 = pk2(p1,p1), pp2 = pk2(p2,p2), pp3 = pk2(p3,p3);
      const ull* row = (const ull*)(kb + (r0 + r)*DKV);
      #pragma unroll
      for (int j = 0; j < 8; j++){
        ull kv = row[j*32 + lane];
        acc[0][j] = ffma2(pp0, kv, acc[0][j]);
        acc[1][j] = ffma2(pp1, kv, acc[1][j]);
        acc[2][j] = ffma2(pp2, kv, acc[2][j]);
        acc[3][j] = ffma2(pp3, kv, acc[3][j]);
      }
    }
  }

  // ---- merge row-half warps and store partials ----
  __syncthreads();
  ull* bufu = (ull*)kvs;
  if (rh == 1){
    #pragma unroll
    for (int h = 0; h < 4; h++)
      #pragma unroll
      for (int j = 0; j < 8; j++)
        bufu[(size_t)(hg + h)*256 + j*32 + lane] = acc[h][j];
    if (myr == 0){ mlx[wg][myh][0] = mh; mlx[wg][myh][1] = lh; }
  }
  __syncthreads();
  if (rh == 0){
    #pragma unroll
    for (int h = 0; h < 4; h++){
      float ma = __shfl_sync(0xffffffffu, mh, h*8);
      float la = __shfl_sync(0xffffffffu, lh, h*8);
      float mb = mlx[wg][h][0], lb = mlx[wg][h][1];
      float nm = fmaxf(ma, mb);
      float ca = __expf(ma - nm), cb = __expf(mb - nm);
      float lm = la*ca + lb*cb;
      int basep = (b*H + hg + h)*NCHUNK + chunk;
      if (lane == 0){ g_m[basep] = nm; g_l[basep] = lm; }
      ull ca2 = pk2(ca,ca), cb2 = pk2(cb,cb);
      ull* op = (ull*)g_opart + (size_t)basep*256;
      #pragma unroll
      for (int j = 0; j < 8; j++)
        op[j*32 + lane] = fadd2(fmul2(acc[h][j], ca2),
                                fmul2(bufu[(size_t)(hg + h)*256 + j*32 + lane], cb2));
    }
  }
}

// ---------------- combine split-softmax partials ----------------
__global__ void __launch_bounds__(128) k_comb(const int* __restrict__ kv_lens){
  int h = blockIdx.x, b = blockIdx.y;
  int tid = threadIdx.x;
  int len = kv_lens[b];
  int cmax = min(NCHUNK - 1, len >> 8);
  int base = (b*H + h)*NCHUNK;
  float mstar = -1e30f;
  for (int c = 0; c <= cmax; c++) mstar = fmaxf(mstar, g_m[base + c]);
  float lstar = 0.f;
  for (int c = 0; c <= cmax; c++) lstar += expf(g_m[base + c] - mstar) * g_l[base + c];
  float inv_l = 1.f / lstar;
  #pragma unroll
  for (int j = 0; j < KV_LORA/128; j++){
    int d = tid + j*128;
    float s = 0.f;
    for (int c = 0; c <= cmax; c++)
      s += expf(g_m[base + c] - mstar) * g_opart[(size_t)(base + c)*KV_LORA + d];
    g_o[(size_t)(b*H + h)*KV_LORA + d] = s * inv_l;
  }
}

// ---------------- t = o @ W_Vd^T (fp8 weights) ----------------
__global__ void __launch_bounds__(256) k_v(){
  int cs = blockIdx.x, h = blockIdx.y;
  int tid = threadIdx.x;
  int vv = tid & 127, rg = tid >> 7;
  __shared__ float ws[128][33];
  __shared__ float os[B][32];
  float invV = g_wscale[1];
  float acc[16];
  #pragma unroll
  for (int i = 0; i < 16; i++) acc[i] = 0.f;
  for (int cbk = 0; cbk < 64; cbk += 32){
    int c0 = cs*64 + cbk;
    __syncthreads();
    #pragma unroll
    for (int it = 0; it < 4; it++){
      int idx = tid + it*256;
      int v = idx >> 3, d4 = (idx & 7)*4;
      const unsigned char* p = g_WV8 + (size_t)(h*VD + v)*KV_LORA + c0 + d4;
      uchar4 u = *(const uchar4*)p;
      ws[v][d4+0]=fp8tf(u.x); ws[v][d4+1]=fp8tf(u.y); ws[v][d4+2]=fp8tf(u.z); ws[v][d4+3]=fp8tf(u.w);
    }
    for (int idx = tid; idx < B*8; idx += 256){
      int r = idx >> 3, d4 = (idx & 7)*4;
      float4 v = *(const float4*)(g_o + (size_t)(r*H + h)*KV_LORA + c0 + d4);
      os[r][d4+0]=v.x; os[r][d4+1]=v.y; os[r][d4+2]=v.z; os[r][d4+3]=v.w;
    }
    __syncthreads();
    #pragma unroll
    for (int d = 0; d < 32; d++){
      float w = ws[vv][d];
      #pragma unroll
      for (int r = 0; r < 16; r++)
        acc[r] += os[rg*16 + r][d]*w;
    }
  }
  #pragma unroll
  for (int r = 0; r < 16; r++){
    int b = rg*16 + r;
    g_t_part[cs][b*HID + h*VD + vv] = acc[r]*invV;
  }
}

__global__ void k_tred(){
  int i = blockIdx.x*blockDim.x + threadIdx.x;
  if (i < B*HID){
    float s = 0.f;
    #pragma unroll
    for (int p = 0; p < VS; p++) s += g_t_part[p][i];
    g_t[i] = s;
  }
}

// ---------------- out = t @ Wo : cp.async staged weights + f32x2 FMA ----------------
__global__ void __launch_bounds__(256) k_out(const float* __restrict__ Wo){
  __shared__ float xs[B][64];
  __shared__ __align__(16) float ws[64][128];
  int cb = blockIdx.x, ks = blockIdx.y;
  int tid = threadIdx.x;
  int tx = tid & 31, ty = tid >> 5;
  int k0 = ks*64;
  {
    int row = tid >> 5;
    int col = (tid & 31)*4;
    #pragma unroll
    for (int s = 0; s < 8; s++){
      int r = s*8 + row;
      const float* src = Wo + (size_t)(k0 + r)*HID + cb*128 + col;
      unsigned sa = (unsigned)__cvta_generic_to_shared(&ws[r][col]);
      asm volatile("cp.async.cg.shared.global [%0], [%1], 16;" :: "r"(sa), "l"(src));
    }
    asm volatile("cp.async.commit_group;" ::: "memory");
  }
  #pragma unroll
  for (int it = 0; it < 2; it++){
    int idx = tid + it*256;
    int r = idx >> 4, c4 = idx & 15;
    float4 v = ((const float4*)g_t)[r*(HID/4) + (k0>>2) + c4];
    xs[r][c4*4+0]=v.x; xs[r][c4*4+1]=v.y; xs[r][c4*4+2]=v.z; xs[r][c4*4+3]=v.w;
  }
  asm volatile("cp.async.wait_group 0;" ::: "memory");
  __syncthreads();
  ull acc[8] = {};
  #pragma unroll 8
  for (int k = 0; k < 64; k++){
    ulonglong2 w2 = ((const ulonglong2*)ws[k])[tx];
    #pragma unroll
    for (int i = 0; i < 4; i++){
      float xv = xs[ty*4+i][k];
      ull xv2 = pk2(xv, xv);
      acc[i*2]   = ffma2(xv2, w2.x, acc[i*2]);
      acc[i*2+1] = ffma2(xv2, w2.y, acc[i*2+1]);
    }
  }
  float4* op = (float4*)g_out_part[ks];
  #pragma unroll
  for (int i = 0; i < 4; i++){
    float2 a = upk2(acc[i*2]), b = upk2(acc[i*2+1]);
    op[(size_t)(ty*4+i)*(HID/4) + cb*32 + tx] = make_float4(a.x,a.y,b.x,b.y);
  }
}

__global__ void k_sum(float* __restrict__ out){
  int i = blockIdx.x*blockDim.x + threadIdx.x;
  if (i < B*HID){
    float s = 0.f;
    #pragma unroll
    for (int ks = 0; ks < KSO; ks++) s += g_out_part[ks][i];
    out[i] = s;
  }
}

extern "C" void kernel_launch(void* const* d_in, const int* in_sizes, int n_in,
                              void* d_out, int out_size){
  const float* q   = (const float*)d_in[0];
  const float* kc  = (const float*)d_in[1];
  const float* kpe = (const float*)d_in[2];
  const float* kvc = (const float*)d_in[3];
  const float* Wq  = (const float*)d_in[4];
  const float* WK  = (const float*)d_in[5];
  const float* WV  = (const float*)d_in[6];
  const float* Wo  = (const float*)d_in[7];
  const int*  lens = (const int*)d_in[8];

  cudaFuncSetAttribute(k_attn, cudaFuncAttributeMaxDynamicSharedMemorySize, 3*TILE*DKV*4);

  k_amax<<<256, 256>>>(WK, WV);
  k_quant<<<512, 256>>>(WK, WV);
  k_qp<<<dim3(NQ/128, KSQ), 256>>>(q, Wq);
  k_qred<<<dim3(B, NQ/512), 256>>>(kc, kpe, lens);
  k_qk<<<dim3(KV_LORA/64, H), 256>>>();
  k_attn<<<dim3(NCHUNK, B), 256, 3*TILE*DKV*4>>>(kvc, lens);
  k_comb<<<dim3(H, B), 128>>>(lens);
  k_v<<<dim3(VS, H), 256>>>();
  k_tred<<<256, 256>>>();
  k_out<<<dim3(HID/128, KSO), 256>>>(Wo);
  k_sum<<<256, 256>>>((float*)d_out);
}

// round 7
// speedup vs baseline: 2.5217x; 1.1433x over previous
#include <cuda_runtime.h>
#include <cuda_fp8.h>
#include <math.h>

#define B 32
#define S 4096
#define H 16
#define KV_LORA 512
#define NOPE 128
#define ROPE 64
#define QKD 192
#define VD 128
#define QIN 1536
#define HID 2048
#define DKV 576
#define NQ (H*QKD)
#define SCALEF 0.07216878364870323f

#define NCHUNK 16
#define CHUNK 256
#define ATILE 8
#define NBUF 4
#define KSQ 8
#define KSO 8
#define VS 8

typedef unsigned long long ull;

// ---------------- packed f32x2 helpers ----------------
__device__ __forceinline__ ull pk2(float x, float y){
  ull r; asm("mov.b64 %0, {%1, %2};" : "=l"(r) : "f"(x), "f"(y)); return r;
}
__device__ __forceinline__ float2 upk2(ull v){
  float2 r; asm("mov.b64 {%0, %1}, %2;" : "=f"(r.x), "=f"(r.y) : "l"(v)); return r;
}
__device__ __forceinline__ ull ffma2(ull a, ull b, ull c){
  ull d; asm("fma.rn.f32x2 %0, %1, %2, %3;" : "=l"(d) : "l"(a), "l"(b), "l"(c)); return d;
}
__device__ __forceinline__ ull fmul2(ull a, ull b){
  ull d; asm("mul.rn.f32x2 %0, %1, %2;" : "=l"(d) : "l"(a), "l"(b)); return d;
}

// ---------------- device scratch ----------------
static __device__ unsigned g_amax[2];                // zero-init; atomicMax idempotent
static __device__ float g_wscale[2];
static __device__ unsigned char g_WK8[H*KV_LORA*NOPE];
static __device__ unsigned char g_WV8[H*VD*KV_LORA];
static __device__ float g_qp_part[KSQ][B*NQ];
static __device__ float g_qn[B*H*NOPE];
static __device__ float g_qf[B*H*DKV];               // pre-scaled by SCALEF
static __device__ float g_newkv[B*DKV];
static __device__ float g_m[B*H*NCHUNK];
static __device__ float g_l[B*H*NCHUNK];
static __device__ float g_opart[B*H*NCHUNK*KV_LORA];
static __device__ float g_o[B*H*KV_LORA];
static __device__ float g_t_part[VS][B*HID];
static __device__ float g_t[B*HID];
static __device__ float g_out_part[KSO][B*HID];

__global__ void k_amax(const float* __restrict__ WK, const float* __restrict__ WV){
  const int N4 = (H*KV_LORA*NOPE)/4;
  const float4* WK4 = (const float4*)WK;
  const float4* WV4 = (const float4*)WV;
  float m0 = 0.f, m1 = 0.f;
  for (int i = blockIdx.x*blockDim.x + threadIdx.x; i < N4; i += gridDim.x*blockDim.x){
    float4 a = WK4[i], b = WV4[i];
    m0 = fmaxf(m0, fmaxf(fmaxf(fabsf(a.x),fabsf(a.y)), fmaxf(fabsf(a.z),fabsf(a.w))));
    m1 = fmaxf(m1, fmaxf(fmaxf(fabsf(b.x),fabsf(b.y)), fmaxf(fabsf(b.z),fabsf(b.w))));
  }
  #pragma unroll
  for (int off = 16; off; off >>= 1){
    m0 = fmaxf(m0, __shfl_xor_sync(0xffffffffu, m0, off));
    m1 = fmaxf(m1, __shfl_xor_sync(0xffffffffu, m1, off));
  }
  __shared__ float s0[8], s1[8];
  int w = threadIdx.x >> 5;
  if ((threadIdx.x & 31) == 0){ s0[w] = m0; s1[w] = m1; }
  __syncthreads();
  if (threadIdx.x == 0){
    #pragma unroll
    for (int i = 1; i < 8; i++){ m0 = fmaxf(m0, s0[i]); m1 = fmaxf(m1, s1[i]); }
    atomicMax(&g_amax[0], __float_as_uint(m0));
    atomicMax(&g_amax[1], __float_as_uint(m1));
  }
}

__device__ __forceinline__ unsigned q8(float v, float s){
  float x = fminf(fmaxf(v*s, -448.f), 448.f);
  return (unsigned)__nv_cvt_float_to_fp8(x, __NV_SATFINITE, __NV_E4M3);
}
__device__ __forceinline__ float fp8tf(unsigned char b){
  __half_raw h = __nv_cvt_fp8_to_halfraw((__nv_fp8_storage_t)b, __NV_E4M3);
  return __half2float(*(__half*)&h);
}

__global__ void k_quant(const float* __restrict__ WK, const float* __restrict__ WV){
  const int N16 = (H*KV_LORA*NOPE)/16;
  float aK = fmaxf(__uint_as_float(g_amax[0]), 1e-10f);
  float aV = fmaxf(__uint_as_float(g_amax[1]), 1e-10f);
  float sK = 448.f / aK, sV = 448.f / aV;
  if (blockIdx.x == 0 && threadIdx.x == 0){ g_wscale[0] = 1.f/sK; g_wscale[1] = 1.f/sV; }
  const float4* WK4 = (const float4*)WK;
  const float4* WV4 = (const float4*)WV;
  uint4* OK = (uint4*)g_WK8;
  uint4* OV = (uint4*)g_WV8;
  for (int i = blockIdx.x*blockDim.x + threadIdx.x; i < N16; i += gridDim.x*blockDim.x){
    uint4 ok, ov;
    unsigned* po = &ok.x;
    unsigned* pv = &ov.x;
    #pragma unroll
    for (int j = 0; j < 4; j++){
      float4 a = WK4[i*4 + j];
      po[j] = q8(a.x,sK) | (q8(a.y,sK)<<8) | (q8(a.z,sK)<<16) | (q8(a.w,sK)<<24);
      float4 b = WV4[i*4 + j];
      pv[j] = q8(b.x,sV) | (q8(b.y,sV)<<8) | (q8(b.z,sV)<<16) | (q8(b.w,sV)<<24);
    }
    OK[i] = ok; OV[i] = ov;
  }
}

// ---------------- qp = q @ Wq : KSQ=8, chunked double-buffered weights ----------------
__global__ void __launch_bounds__(256) k_qp(const float* __restrict__ q,
                                            const float* __restrict__ Wq){
  __shared__ float xs[B][192];
  __shared__ __align__(16) float ws[2][32][64];
  int cb = blockIdx.x, ks = blockIdx.y;
  int tid = threadIdx.x;
  int tx = tid & 15, ty = tid >> 4;
  int k0 = ks*192;
  #pragma unroll
  for (int it = 0; it < 6; it++){
    int idx = tid + it*256;
    int r = idx/48, c4 = idx - r*48;
    float4 v = ((const float4*)q)[r*(QIN/4) + (k0>>2) + c4];
    *(float4*)&xs[r][c4*4] = v;
  }
  auto loadw = [&](int c){
    int buf = c & 1;
    #pragma unroll
    for (int it = 0; it < 2; it++){
      int idx = tid + it*256;
      int r = idx >> 4, c4 = idx & 15;
      const float* src = Wq + (size_t)(k0 + c*32 + r)*NQ + cb*64 + c4*4;
      unsigned sa = (unsigned)__cvta_generic_to_shared(&ws[buf][r][c4*4]);
      asm volatile("cp.async.cg.shared.global [%0], [%1], 16;" :: "r"(sa), "l"(src));
    }
    asm volatile("cp.async.commit_group;" ::: "memory");
  };
  loadw(0);
  ull acc[2][2] = {};
  for (int c = 0; c < 6; c++){
    if (c < 5){
      loadw(c+1);
      asm volatile("cp.async.wait_group 1;" ::: "memory");
    } else {
      asm volatile("cp.async.wait_group 0;" ::: "memory");
    }
    __syncthreads();
    int buf = c & 1;
    #pragma unroll
    for (int k = 0; k < 32; k++){
      ulonglong2 w2 = ((const ulonglong2*)&ws[buf][k][0])[tx];
      #pragma unroll
      for (int i = 0; i < 2; i++){
        float xv = xs[ty*2+i][c*32+k];
        ull xv2 = pk2(xv, xv);
        acc[i][0] = ffma2(xv2, w2.x, acc[i][0]);
        acc[i][1] = ffma2(xv2, w2.y, acc[i][1]);
      }
    }
    __syncthreads();
  }
  float4* op = (float4*)g_qp_part[ks];
  #pragma unroll
  for (int i = 0; i < 2; i++){
    float2 a = upk2(acc[i][0]), b2 = upk2(acc[i][1]);
    op[(size_t)(ty*2+i)*(NQ/4) + cb*16 + tx] = make_float4(a.x,a.y,b2.x,b2.y);
  }
}

// ---------------- reduce qp partials + rope + new_kv ----------------
__global__ void __launch_bounds__(256) k_qred(const float* __restrict__ kc,
                                              const float* __restrict__ kpe,
                                              const int* __restrict__ kv_lens){
  int b = blockIdx.x, cy = blockIdx.y;
  int tid = threadIdx.x;
  __shared__ float qs[512];
  int cbase = cy*512;
  #pragma unroll
  for (int j = 0; j < 2; j++){
    int col = tid + j*256;
    float s = 0.f;
    #pragma unroll
    for (int ks = 0; ks < KSQ; ks++) s += g_qp_part[ks][b*NQ + cbase + col];
    qs[col] = s;
  }
  __syncthreads();
  int pos = kv_lens[b];
  #pragma unroll
  for (int j = 0; j < 2; j++){
    int col = tid + j*256;
    int gc = cbase + col;
    int h = gc/192, off = gc - h*192;
    if (off < 128){
      g_qn[(b*H + h)*NOPE + off] = qs[col];
    } else if (off < 160){
      int i = off - 128;
      double inv = exp(-((2.0*i)/64.0) * 9.210340371976184);
      double ang = (double)pos * inv;
      float cs = (float)cos(ang), sn = (float)sin(ang);
      float x1 = qs[col], x2 = qs[col+32];
      float* qf = g_qf + (size_t)(b*H + h)*DKV;
      qf[KV_LORA + i]      = (x1*cs - x2*sn)*SCALEF;
      qf[KV_LORA + 32 + i] = (x2*cs + x1*sn)*SCALEF;
    }
  }
  if (cy == 0){
    for (int j = tid; j < KV_LORA; j += 256) g_newkv[b*DKV + j] = kc[b*KV_LORA + j];
    if (tid < 32){
      int i = tid;
      double inv = exp(-((2.0*i)/64.0)*9.210340371976184);
      double ang = (double)pos*inv;
      float cs = (float)cos(ang), sn = (float)sin(ang);
      float k1 = kpe[b*ROPE + i], k2 = kpe[b*ROPE + 32 + i];
      g_newkv[b*DKV + KV_LORA + i]      = k1*cs - k2*sn;
      g_newkv[b*DKV + KV_LORA + 32 + i] = k2*cs + k1*sn;
    }
  }
}

// ---------------- ql_nope = q_nope @ W_Kd^T (fp8 weights) ----------------
__global__ void __launch_bounds__(256) k_qk(){
  int h = blockIdx.y, c0 = blockIdx.x*64;
  int tid = threadIdx.x;
  int cc = tid & 63, rg = tid >> 6;
  __shared__ float qn_s[B][NOPE];
  __shared__ float ws[64][33];
  float invK = g_wscale[0];
  for (int idx = tid; idx < B*(NOPE/4); idx += 256){
    int r = idx >> 5, d4 = idx & 31;
    float4 v = ((const float4*)(g_qn + (size_t)(r*H + h)*NOPE))[d4];
    qn_s[r][d4*4+0]=v.x; qn_s[r][d4*4+1]=v.y; qn_s[r][d4*4+2]=v.z; qn_s[r][d4*4+3]=v.w;
  }
  float acc[8];
  #pragma unroll
  for (int i = 0; i < 8; i++) acc[i] = 0.f;
  for (int db = 0; db < NOPE; db += 32){
    __syncthreads();
    #pragma unroll
    for (int it = 0; it < 2; it++){
      int idx = tid + it*256;
      int c = idx >> 3, d4 = (idx & 7)*4;
      const unsigned char* p = g_WK8 + (size_t)(h*KV_LORA + c0 + c)*NOPE + db + d4;
      uchar4 v = *(const uchar4*)p;
      ws[c][d4+0]=fp8tf(v.x); ws[c][d4+1]=fp8tf(v.y); ws[c][d4+2]=fp8tf(v.z); ws[c][d4+3]=fp8tf(v.w);
    }
    __syncthreads();
    #pragma unroll
    for (int d = 0; d < 32; d++){
      float w = ws[cc][d];
      #pragma unroll
      for (int r = 0; r < 8; r++)
        acc[r] += qn_s[rg*8 + r][db + d]*w;
    }
  }
  float sc = SCALEF*invK;
  #pragma unroll
  for (int r = 0; r < 8; r++){
    int b = rg*8 + r;
    g_qf[(size_t)(b*H + h)*DKV + c0 + cc] = acc[r]*sc;
  }
}

// ---------------- flash attention: 128 thr, 2 CTA/SM, TILE=8, 4-deep pipeline ----------------
__global__ void __launch_bounds__(128, 2) k_attn(const float* __restrict__ kv_cache,
                                                 const int* __restrict__ kv_lens){
  extern __shared__ float kvs[];   // [NBUF][ATILE][DKV]
  __shared__ float ps[4][32];
  int chunk = blockIdx.x, b = blockIdx.y;
  int len = kv_lens[b];
  int s_begin = chunk*CHUNK;
  if (s_begin > len) return;
  int s_end = min(s_begin + CHUNK, len + 1);
  int T = (s_end - s_begin + ATILE - 1)/ATILE;

  int tid = threadIdx.x;
  int warp = tid >> 5, lane = tid & 31;
  int myh = lane >> 3, myr = lane & 7;

  // q registers: 4 heads, float4-granular layout
  ulonglong2 q4[4][4]; ull qt[4];
  #pragma unroll
  for (int h = 0; h < 4; h++){
    const float* qf = g_qf + (size_t)(b*H + warp*4 + h)*DKV;
    #pragma unroll
    for (int j = 0; j < 4; j++) q4[h][j] = ((const ulonglong2*)qf)[j*32 + lane];
    qt[h] = ((const ull*)qf)[256 + lane];
  }

  ull acc[4][8];
  #pragma unroll
  for (int h = 0; h < 4; h++)
    #pragma unroll
    for (int j = 0; j < 8; j++) acc[h][j] = 0ull;
  float mh = -1e30f, lh = 0.f;

  auto load_tile = [&](int t){
    int buf = t & (NBUF-1);
    int t0 = s_begin + t*ATILE;
    int rows = min(ATILE, s_end - t0);
    float* dst = kvs + buf*(ATILE*DKV);
    for (int idx = tid; idx < rows*144; idx += 128){
      int r = idx/144, c4 = idx - r*144;
      int s = t0 + r;
      const float* src = (s == len) ? (g_newkv + b*DKV + c4*4)
                                    : (kv_cache + ((size_t)b*S + s)*DKV + c4*4);
      unsigned sa = (unsigned)__cvta_generic_to_shared(dst + r*DKV + c4*4);
      asm volatile("cp.async.cg.shared.global [%0], [%1], 16;" :: "r"(sa), "l"(src));
    }
    if (rows < ATILE)
      for (int idx = tid + rows*144; idx < ATILE*144; idx += 128){
        int r = idx/144, c4 = idx - r*144;
        *(float4*)(dst + r*DKV + c4*4) = make_float4(0.f,0.f,0.f,0.f);
      }
    asm volatile("cp.async.commit_group;" ::: "memory");
  };

  load_tile(0);
  if (T > 1) load_tile(1);
  if (T > 2) load_tile(2);
  for (int t = 0; t < T; t++){
    int rem = T - 1 - t;
    if (rem >= 2)      asm volatile("cp.async.wait_group 2;" ::: "memory");
    else if (rem == 1) asm volatile("cp.async.wait_group 1;" ::: "memory");
    else               asm volatile("cp.async.wait_group 0;" ::: "memory");
    __syncthreads();
    if (t + 3 < T) load_tile(t+3);

    const float* kb = kvs + (t & (NBUF-1))*(ATILE*DKV);
    int t0 = s_begin + t*ATILE;

    // ---- scores: 4 heads x 8 rows ----
    float x[32];
    #pragma unroll
    for (int r = 0; r < 8; r++){
      const ulonglong2* row4 = (const ulonglong2*)(kb + r*DKV);
      ull s0=0, s1=0, s2=0, s3=0;
      #pragma unroll
      for (int j = 0; j < 4; j++){
        ulonglong2 kv = row4[j*32 + lane];
        s0 = ffma2(q4[0][j].x, kv.x, s0); s0 = ffma2(q4[0][j].y, kv.y, s0);
        s1 = ffma2(q4[1][j].x, kv.x, s1); s1 = ffma2(q4[1][j].y, kv.y, s1);
        s2 = ffma2(q4[2][j].x, kv.x, s2); s2 = ffma2(q4[2][j].y, kv.y, s2);
        s3 = ffma2(q4[3][j].x, kv.x, s3); s3 = ffma2(q4[3][j].y, kv.y, s3);
      }
      ull kt = ((const ull*)(kb + r*DKV))[256 + lane];
      s0 = ffma2(qt[0], kt, s0);
      s1 = ffma2(qt[1], kt, s1);
      s2 = ffma2(qt[2], kt, s2);
      s3 = ffma2(qt[3], kt, s3);
      float2 v0=upk2(s0), v1=upk2(s1), v2=upk2(s2), v3=upk2(s3);
      x[0*8+r] = v0.x+v0.y; x[1*8+r] = v1.x+v1.y;
      x[2*8+r] = v2.x+v2.y; x[3*8+r] = v3.x+v3.y;
    }
    // fold: lane L ends with total of value L (h = L>>3, r = L&7)
    #pragma unroll
    for (int off = 16; off >= 1; off >>= 1){
      bool hi = (lane & off) != 0;
      #pragma unroll
      for (int i = 0; i < off; i++){
        float send = hi ? x[i] : x[i+off];
        float recv = __shfl_xor_sync(0xffffffffu, send, off);
        x[i] = (hi ? x[i+off] : x[i]) + recv;
      }
    }
    bool valid = (t0 + myr) < s_end;
    float sc = valid ? x[0] : -1e30f;

    float tm = sc;
    tm = fmaxf(tm, __shfl_xor_sync(0xffffffffu, tm, 4));
    tm = fmaxf(tm, __shfl_xor_sync(0xffffffffu, tm, 2));
    tm = fmaxf(tm, __shfl_xor_sync(0xffffffffu, tm, 1));
    float nm = fmaxf(mh, tm);
    float cf = __expf(mh - nm);
    mh = nm;
    float p = valid ? __expf(sc - nm) : 0.f;
    float sp = p;
    sp += __shfl_xor_sync(0xffffffffu, sp, 4);
    sp += __shfl_xor_sync(0xffffffffu, sp, 2);
    sp += __shfl_xor_sync(0xffffffffu, sp, 1);
    lh = lh*cf + sp;

    ps[warp][myr*4 + myh] = p;
    #pragma unroll
    for (int h = 0; h < 4; h++){
      float cfh = __shfl_sync(0xffffffffu, cf, h*8);
      ull c2 = pk2(cfh, cfh);
      #pragma unroll
      for (int j = 0; j < 8; j++) acc[h][j] = fmul2(acc[h][j], c2);
    }
    __syncwarp();

    // ---- accumulate (first 512 dims) ----
    #pragma unroll
    for (int r = 0; r < 8; r++){
      float4 pv = *(const float4*)&ps[warp][r*4];
      ull pp0 = pk2(pv.x,pv.x), pp1 = pk2(pv.y,pv.y), pp2 = pk2(pv.z,pv.z), pp3 = pk2(pv.w,pv.w);
      const ulonglong2* row4 = (const ulonglong2*)(kb + r*DKV);
      #pragma unroll
      for (int j = 0; j < 4; j++){
        ulonglong2 kv = row4[j*32 + lane];
        acc[0][2*j]   = ffma2(pp0, kv.x, acc[0][2*j]);
        acc[0][2*j+1] = ffma2(pp0, kv.y, acc[0][2*j+1]);
        acc[1][2*j]   = ffma2(pp1, kv.x, acc[1][2*j]);
        acc[1][2*j+1] = ffma2(pp1, kv.y, acc[1][2*j+1]);
        acc[2][2*j]   = ffma2(pp2, kv.x, acc[2][2*j]);
        acc[2][2*j+1] = ffma2(pp2, kv.y, acc[2][2*j+1]);
        acc[3][2*j]   = ffma2(pp3, kv.x, acc[3][2*j]);
        acc[3][2*j+1] = ffma2(pp3, kv.y, acc[3][2*j+1]);
      }
    }
  }

  // ---- store partials (no cross-warp merge needed) ----
  #pragma unroll
  for (int h = 0; h < 4; h++){
    int basep = (b*H + warp*4 + h)*NCHUNK + chunk;
    if (lane == h*8){ g_m[basep] = mh; g_l[basep] = lh; }
    ull* op = (ull*)g_opart + (size_t)basep*256;
    #pragma unroll
    for (int j = 0; j < 4; j++){
      op[j*64 + lane*2]     = acc[h][2*j];
      op[j*64 + lane*2 + 1] = acc[h][2*j+1];
    }
  }
}

// ---------------- combine split-softmax partials ----------------
__global__ void __launch_bounds__(128) k_comb(const int* __restrict__ kv_lens){
  int h = blockIdx.x, b = blockIdx.y;
  int tid = threadIdx.x;
  int len = kv_lens[b];
  int cmax = min(NCHUNK - 1, len >> 8);
  int base = (b*H + h)*NCHUNK;
  float mstar = -1e30f;
  for (int c = 0; c <= cmax; c++) mstar = fmaxf(mstar, g_m[base + c]);
  float lstar = 0.f;
  for (int c = 0; c <= cmax; c++) lstar += expf(g_m[base + c] - mstar) * g_l[base + c];
  float inv_l = 1.f / lstar;
  #pragma unroll
  for (int j = 0; j < KV_LORA/128; j++){
    int d = tid + j*128;
    float s = 0.f;
    for (int c = 0; c <= cmax; c++)
      s += expf(g_m[base + c] - mstar) * g_opart[(size_t)(base + c)*KV_LORA + d];
    g_o[(size_t)(b*H + h)*KV_LORA + d] = s * inv_l;
  }
}

// ---------------- t = o @ W_Vd^T (fp8 weights) ----------------
__global__ void __launch_bounds__(256) k_v(){
  int cs = blockIdx.x, h = blockIdx.y;
  int tid = threadIdx.x;
  int vv = tid & 127, rg = tid >> 7;
  __shared__ float ws[128][33];
  __shared__ float os[B][32];
  float invV = g_wscale[1];
  float acc[16];
  #pragma unroll
  for (int i = 0; i < 16; i++) acc[i] = 0.f;
  for (int cbk = 0; cbk < 64; cbk += 32){
    int c0 = cs*64 + cbk;
    __syncthreads();
    #pragma unroll
    for (int it = 0; it < 4; it++){
      int idx = tid + it*256;
      int v = idx >> 3, d4 = (idx & 7)*4;
      const unsigned char* p = g_WV8 + (size_t)(h*VD + v)*KV_LORA + c0 + d4;
      uchar4 u = *(const uchar4*)p;
      ws[v][d4+0]=fp8tf(u.x); ws[v][d4+1]=fp8tf(u.y); ws[v][d4+2]=fp8tf(u.z); ws[v][d4+3]=fp8tf(u.w);
    }
    for (int idx = tid; idx < B*8; idx += 256){
      int r = idx >> 3, d4 = (idx & 7)*4;
      float4 v = *(const float4*)(g_o + (size_t)(r*H + h)*KV_LORA + c0 + d4);
      os[r][d4+0]=v.x; os[r][d4+1]=v.y; os[r][d4+2]=v.z; os[r][d4+3]=v.w;
    }
    __syncthreads();
    #pragma unroll
    for (int d = 0; d < 32; d++){
      float w = ws[vv][d];
      #pragma unroll
      for (int r = 0; r < 16; r++)
        acc[r] += os[rg*16 + r][d]*w;
    }
  }
  #pragma unroll
  for (int r = 0; r < 16; r++){
    int b = rg*16 + r;
    g_t_part[cs][b*HID + h*VD + vv] = acc[r]*invV;
  }
}

__global__ void k_tred(){
  int i = blockIdx.x*blockDim.x + threadIdx.x;
  if (i < B*HID){
    float s = 0.f;
    #pragma unroll
    for (int p = 0; p < VS; p++) s += g_t_part[p][i];
    g_t[i] = s;
  }
}

// ---------------- out = t @ Wo : KSO=8, chunked double-buffered weights ----------------
__global__ void __launch_bounds__(256) k_out(const float* __restrict__ Wo){
  __shared__ float xs[B][256];
  __shared__ __align__(16) float ws[2][32][64];
  int cb = blockIdx.x, ks = blockIdx.y;
  int tid = threadIdx.x;
  int tx = tid & 15, ty = tid >> 4;
  int k0 = ks*256;
  #pragma unroll
  for (int it = 0; it < 8; it++){
    int idx = tid + it*256;
    int r = idx >> 6, c4 = idx & 63;
    float4 v = ((const float4*)g_t)[r*(HID/4) + (k0>>2) + c4];
    *(float4*)&xs[r][c4*4] = v;
  }
  auto loadw = [&](int c){
    int buf = c & 1;
    #pragma unroll
    for (int it = 0; it < 2; it++){
      int idx = tid + it*256;
      int r = idx >> 4, c4 = idx & 15;
      const float* src = Wo + (size_t)(k0 + c*32 + r)*HID + cb*64 + c4*4;
      unsigned sa = (unsigned)__cvta_generic_to_shared(&ws[buf][r][c4*4]);
      asm volatile("cp.async.cg.shared.global [%0], [%1], 16;" :: "r"(sa), "l"(src));
    }
    asm volatile("cp.async.commit_group;" ::: "memory");
  };
  loadw(0);
  ull acc[2][2] = {};
  for (int c = 0; c < 8; c++){
    if (c < 7){
      loadw(c+1);
      asm volatile("cp.async.wait_group 1;" ::: "memory");
    } else {
      asm volatile("cp.async.wait_group 0;" ::: "memory");
    }
    __syncthreads();
    int buf = c & 1;
    #pragma unroll
    for (int k = 0; k < 32; k++){
      ulonglong2 w2 = ((const ulonglong2*)&ws[buf][k][0])[tx];
      #pragma unroll
      for (int i = 0; i < 2; i++){
        float xv = xs[ty*2+i][c*32+k];
        ull xv2 = pk2(xv, xv);
        acc[i][0] = ffma2(xv2, w2.x, acc[i][0]);
        acc[i][1] = ffma2(xv2, w2.y, acc[i][1]);
      }
    }
    __syncthreads();
  }
  float4* op = (float4*)g_out_part[ks];
  #pragma unroll
  for (int i = 0; i < 2; i++){
    float2 a = upk2(acc[i][0]), b2 = upk2(acc[i][1]);
    op[(size_t)(ty*2+i)*(HID/4) + cb*16 + tx] = make_float4(a.x,a.y,b2.x,b2.y);
  }
}

__global__ void k_sum(float* __restrict__ out){
  int i = blockIdx.x*blockDim.x + threadIdx.x;
  if (i < B*HID){
    float s = 0.f;
    #pragma unroll
    for (int ks = 0; ks < KSO; ks++) s += g_out_part[ks][i];
    out[i] = s;
  }
}

extern "C" void kernel_launch(void* const* d_in, const int* in_sizes, int n_in,
                              void* d_out, int out_size){
  const float* q   = (const float*)d_in[0];
  const float* kc  = (const float*)d_in[1];
  const float* kpe = (const float*)d_in[2];
  const float* kvc = (const float*)d_in[3];
  const float* Wq  = (const float*)d_in[4];
  const float* WK  = (const float*)d_in[5];
  const float* WV  = (const float*)d_in[6];
  const float* Wo  = (const float*)d_in[7];
  const int*  lens = (const int*)d_in[8];

  cudaFuncSetAttribute(k_attn, cudaFuncAttributeMaxDynamicSharedMemorySize, NBUF*ATILE*DKV*4);

  k_amax<<<256, 256>>>(WK, WV);
  k_quant<<<512, 256>>>(WK, WV);
  k_qp<<<dim3(NQ/64, KSQ), 256>>>(q, Wq);
  k_qred<<<dim3(B, NQ/512), 256>>>(kc, kpe, lens);
  k_qk<<<dim3(KV_LORA/64, H), 256>>>();
  k_attn<<<dim3(NCHUNK, B), 128, NBUF*ATILE*DKV*4>>>(kvc, lens);
  k_comb<<<dim3(H, B), 128>>>(lens);
  k_v<<<dim3(VS, H), 256>>>();
  k_tred<<<256, 256>>>();
  k_out<<<dim3(HID/64, KSO), 256>>>(Wo);
  k_sum<<<256, 256>>>((float*)d_out);
}